// round 15
// baseline (speedup 1.0000x reference)
#include <cuda_runtime.h>
#include <cuda_fp16.h>
#include <math.h>
#include <stdint.h>

// ---------------- problem constants ----------------
#define BB 2
#define SS 512
#define CC 512
#define LL 1024
#define HH 1024
#define NHEAD 16
#define HD 64
#define FF 4096
#define NLAYER 4
#define VV 32000
#define TDIM 512
#define NEGINF (-1000000000.0f)

// ---------------- scratch (device globals; no allocs allowed) ----------------
__device__ float g_x  [BB*LL*HH];
__device__ float g_hr [BB*SS*TDIM];
__device__ unsigned char g_pad[BB*LL];
__device__ uint32_t g_mask[BB*LL*32];

__device__ __half g_xnh [BB*LL*HH];
__device__ __half g_qh  [BB*LL*HH];
__device__ __half g_kh  [BB*LL*HH];
__device__ __half g_vh  [BB*LL*HH];
__device__ __half g_atth[BB*LL*HH];
__device__ __half g_m1h [BB*LL*FF];
__device__ __half g_xch [BB*SS*(HH+TDIM)];
__device__ __half g_h1h [BB*SS*HH];

// half weight pool
#define WH_TOTAL 136577024
__device__ __half g_wh[WH_TOTAL];

// ---------------- block reductions ----------------
__device__ __forceinline__ float block_reduce_sum(float v, float* red) {
    int t = threadIdx.x, lane = t & 31, w = t >> 5;
    #pragma unroll
    for (int o = 16; o > 0; o >>= 1) v += __shfl_xor_sync(0xffffffffu, v, o);
    if (lane == 0) red[w] = v;
    __syncthreads();
    int nw = (blockDim.x + 31) >> 5;
    float r = (t < nw) ? red[t] : 0.f;
    if (w == 0) {
        #pragma unroll
        for (int o = 16; o > 0; o >>= 1) r += __shfl_xor_sync(0xffffffffu, r, o);
        if (t == 0) red[0] = r;
    }
    __syncthreads();
    float out = red[0];
    __syncthreads();
    return out;
}

__device__ __forceinline__ float block_reduce_max(float v, float* red) {
    int t = threadIdx.x, lane = t & 31, w = t >> 5;
    #pragma unroll
    for (int o = 16; o > 0; o >>= 1) v = fmaxf(v, __shfl_xor_sync(0xffffffffu, v, o));
    if (lane == 0) red[w] = v;
    __syncthreads();
    int nw = (blockDim.x + 31) >> 5;
    float r = (t < nw) ? red[t] : -3.4e38f;
    if (w == 0) {
        #pragma unroll
        for (int o = 16; o > 0; o >>= 1) r = fmaxf(r, __shfl_xor_sync(0xffffffffu, r, o));
        if (t == 0) red[0] = r;
    }
    __syncthreads();
    float out = red[0];
    __syncthreads();
    return out;
}

// ---------------- async copy / ldmatrix helpers ----------------
__device__ __forceinline__ void cp_async16(void* dst, const void* src) {
    uint32_t d = (uint32_t)__cvta_generic_to_shared(dst);
    asm volatile("cp.async.cg.shared.global [%0], [%1], 16;\n" :: "r"(d), "l"(src));
}
#define CP_ASYNC_COMMIT() asm volatile("cp.async.commit_group;\n" ::)
#define CP_ASYNC_WAIT(N)  asm volatile("cp.async.wait_group %0;\n" :: "n"(N))

__device__ __forceinline__ void ldsm_x4(uint32_t& r0, uint32_t& r1, uint32_t& r2, uint32_t& r3, uint32_t addr) {
    asm volatile("ldmatrix.sync.aligned.m8n8.x4.shared.b16 {%0,%1,%2,%3}, [%4];"
        : "=r"(r0), "=r"(r1), "=r"(r2), "=r"(r3) : "r"(addr));
}
__device__ __forceinline__ void ldsm_x4t(uint32_t& r0, uint32_t& r1, uint32_t& r2, uint32_t& r3, uint32_t addr) {
    asm volatile("ldmatrix.sync.aligned.m8n8.x4.trans.shared.b16 {%0,%1,%2,%3}, [%4];"
        : "=r"(r0), "=r"(r1), "=r"(r2), "=r"(r3) : "r"(addr));
}
__device__ __forceinline__ void ldsm_x2(uint32_t& r0, uint32_t& r1, uint32_t addr) {
    asm volatile("ldmatrix.sync.aligned.m8n8.x2.shared.b16 {%0,%1}, [%2];"
        : "=r"(r0), "=r"(r1) : "r"(addr));
}
__device__ __forceinline__ void ldsm_x2t(uint32_t& r0, uint32_t& r1, uint32_t addr) {
    asm volatile("ldmatrix.sync.aligned.m8n8.x2.trans.shared.b16 {%0,%1}, [%2];"
        : "=r"(r0), "=r"(r1) : "r"(addr));
}
__device__ __forceinline__ void mma_f16(float* c, uint32_t a0, uint32_t a1, uint32_t a2, uint32_t a3,
                                        uint32_t b0, uint32_t b1) {
    asm volatile(
        "mma.sync.aligned.m16n8k16.row.col.f32.f16.f16.f32 "
        "{%0,%1,%2,%3}, {%4,%5,%6,%7}, {%8,%9}, {%0,%1,%2,%3};"
        : "+f"(c[0]), "+f"(c[1]), "+f"(c[2]), "+f"(c[3])
        : "r"(a0), "r"(a1), "r"(a2), "r"(a3), "r"(b0), "r"(b1));
}

// ---------------- fp16 tensor-core GEMM, BK=64, 3-stage, single-sync multistage ----------------
// Block tile 128x128, BK=64, 256 threads = 8 warps (2m x 4n), warp tile 64x32.
// Epilogue modes: 0:+bias->Cf  1:Cf+=  2:+bias,silu->Cf  3:+bias,silu->Ch  5:->Ch  6:vv*Ch->Ch
#define NSTAGE 3
#define HA_STRIDE 72
#define HB_STRIDE 136
#define HA_STAGE (128*HA_STRIDE)
#define HB_STAGE (64*HB_STRIDE)
#define HGEMM_SMEM_BYTES ((NSTAGE*(HA_STAGE + HB_STAGE)) * 2)

template<int EPI>
__device__ __forceinline__ void hgemm_core(const __half* __restrict__ A, const __half* __restrict__ Bm,
                                           const float* __restrict__ bias,
                                           float* __restrict__ Cf, __half* __restrict__ Ch,
                                           int M, int N, int K, __half* sm) {
    __half* sA = sm;
    __half* sB = sm + NSTAGE * HA_STAGE;
    const int tid = threadIdx.x;
    const int lane = tid & 31;
    const int warp = tid >> 5;
    const int warp_m = warp >> 2;
    const int warp_n = warp & 3;
    const int g  = lane >> 2;
    const int t4 = lane & 3;
    const int bm = blockIdx.y;
    const int bn = blockIdx.x;

    float acc[4][4][4] = {};

    // fills: A row=tid>>1 (0..127), col=(tid&1)*32 (4 chunks); B row=tid>>2 (0..63), col=(tid&3)*32 (4 chunks)
    const int a_row = tid >> 1;
    const int a_col = (tid & 1) * 32;
    const int b_row = tid >> 2;
    const int b_col = (tid & 3) * 32;
    const __half* Agp = A  + (size_t)(bm * 128 + a_row) * K + a_col;
    const __half* Bgp = Bm + (size_t)b_row * N + (size_t)bn * 128 + b_col;

    const int KT = K >> 6;

    uint32_t sA_b = (uint32_t)__cvta_generic_to_shared(sA);
    uint32_t sB_b = (uint32_t)__cvta_generic_to_shared(sB);
    uint32_t aBase = sA_b + (uint32_t)(((warp_m * 64 + (lane & 15)) * HA_STRIDE + (lane >> 4) * 8) * 2);
    uint32_t bBase = sB_b + (uint32_t)(((((lane >> 3) & 1) * 8 + (lane & 7)) * HB_STRIDE
                                       + warp_n * 32 + (lane >> 4) * 8) * 2);

    // prologue: fill stages 0..NSTAGE-2
    #pragma unroll
    for (int s = 0; s < NSTAGE - 1; s++) {
        __half* da = sA + s * HA_STAGE + a_row * HA_STRIDE + a_col;
        __half* db = sB + s * HB_STAGE + b_row * HB_STRIDE + b_col;
        const __half* ga = Agp + s * 64;
        const __half* gb = Bgp + (size_t)s * 64 * N;
        #pragma unroll
        for (int j = 0; j < 4; j++) {
            cp_async16(da + j * 8, ga + j * 8);
            cp_async16(db + j * 8, gb + j * 8);
        }
        CP_ASYNC_COMMIT();
    }

    for (int kt = 0; kt < KT; kt++) {
        CP_ASYNC_WAIT(NSTAGE - 2);
        __syncthreads();

        // prefetch stage kt+NSTAGE-1 (issued after barrier -> slot safe to reuse)
        if (kt + NSTAGE - 1 < KT) {
            int slot_w = (kt + NSTAGE - 1) % NSTAGE;
            __half* da = sA + slot_w * HA_STAGE + a_row * HA_STRIDE + a_col;
            __half* db = sB + slot_w * HB_STAGE + b_row * HB_STRIDE + b_col;
            const __half* ga = Agp + (kt + NSTAGE - 1) * 64;
            const __half* gb = Bgp + (size_t)(kt + NSTAGE - 1) * 64 * N;
            #pragma unroll
            for (int j = 0; j < 4; j++) {
                cp_async16(da + j * 8, ga + j * 8);
                cp_async16(db + j * 8, gb + j * 8);
            }
        }
        CP_ASYNC_COMMIT();

        int slot = kt % NSTAGE;
        uint32_t aSt = aBase + (uint32_t)(slot * HA_STAGE * 2);
        uint32_t bSt = bBase + (uint32_t)(slot * HB_STAGE * 2);

        #pragma unroll
        for (int ks = 0; ks < 4; ks++) {
            uint32_t af[4][4], bf[4][2];
            #pragma unroll
            for (int mt = 0; mt < 4; mt++)
                ldsm_x4(af[mt][0], af[mt][1], af[mt][2], af[mt][3],
                        aSt + (uint32_t)(mt * 16 * HA_STRIDE * 2 + ks * 32));
            #pragma unroll
            for (int pr = 0; pr < 2; pr++)
                ldsm_x4t(bf[pr*2][0], bf[pr*2][1], bf[pr*2+1][0], bf[pr*2+1][1],
                         bSt + (uint32_t)((ks * 16 * HB_STRIDE + pr * 16) * 2));
            #pragma unroll
            for (int mt = 0; mt < 4; mt++)
                #pragma unroll
                for (int nt = 0; nt < 4; nt++)
                    mma_f16(acc[mt][nt], af[mt][0], af[mt][1], af[mt][2], af[mt][3],
                            bf[nt][0], bf[nt][1]);
        }
    }

    #pragma unroll
    for (int mt = 0; mt < 4; mt++) {
        int row0 = bm * 128 + warp_m * 64 + mt * 16 + g;
        #pragma unroll
        for (int nt = 0; nt < 4; nt++) {
            int col0 = bn * 128 + warp_n * 32 + nt * 8 + t4 * 2;
            #pragma unroll
            for (int f = 0; f < 4; f++) {
                int r = row0 + ((f & 2) ? 8 : 0);
                int c = col0 + (f & 1);
                float vv = acc[mt][nt][f];
                size_t idx = (size_t)r * N + c;
                if (EPI == 0) {
                    if (bias) vv += bias[c];
                    Cf[idx] = vv;
                } else if (EPI == 1) {
                    Cf[idx] += vv;
                } else if (EPI == 2) {
                    if (bias) vv += bias[c];
                    vv = vv / (1.f + expf(-vv));
                    Cf[idx] = vv;
                } else if (EPI == 3) {
                    if (bias) vv += bias[c];
                    vv = vv / (1.f + expf(-vv));
                    Ch[idx] = __float2half_rn(vv);
                } else if (EPI == 6) {
                    vv *= __half2float(Ch[idx]);
                    Ch[idx] = __float2half_rn(vv);
                } else {
                    Ch[idx] = __float2half_rn(vv);
                }
            }
        }
    }
}

template<int EPI>
__global__ __launch_bounds__(256, 2)
void hgemm_kernel(const __half* __restrict__ A, const __half* __restrict__ Bm,
                  const float* __restrict__ bias, float* __restrict__ Cf, __half* __restrict__ Ch,
                  int M, int N, int K) {
    extern __shared__ __half smh[];
    hgemm_core<EPI>(A, Bm, bias, Cf, Ch, M, N, K, smh);
}

struct QKVPtrsH { const __half *Bq, *Bk, *Bv; __half *Cq, *Ck, *Cv; };

__global__ __launch_bounds__(256, 2)
void hgemm_qkv_kernel(const __half* __restrict__ A, QKVPtrsH p, int M, int N, int K) {
    extern __shared__ __half smh[];
    const __half* Bm = (blockIdx.z == 0) ? p.Bq : (blockIdx.z == 1) ? p.Bk : p.Bv;
    __half*       Cm = (blockIdx.z == 0) ? p.Cq : (blockIdx.z == 1) ? p.Ck : p.Cv;
    hgemm_core<5>(A, Bm, nullptr, nullptr, Cm, M, N, K, smh);
}

// ---------------- fp32 -> fp16: coalesced grid-stride, 4 independent loads ----------------
__global__ void f2h_kernel(const float* __restrict__ src, __half* __restrict__ dst, int T) {
    int i = blockIdx.x * blockDim.x + threadIdx.x;
    if (i >= T) return;
    const float4* s = (const float4*)src;
    __half2* d = (__half2*)dst;
    float4 v0 = s[i];
    float4 v1 = s[i + T];
    float4 v2 = s[i + 2 * T];
    float4 v3 = s[i + 3 * T];
    d[2*(i)         ] = __floats2half2_rn(v0.x, v0.y);
    d[2*(i)      + 1] = __floats2half2_rn(v0.z, v0.w);
    d[2*(i +   T)   ] = __floats2half2_rn(v1.x, v1.y);
    d[2*(i +   T)+ 1] = __floats2half2_rn(v1.z, v1.w);
    d[2*(i + 2*T)   ] = __floats2half2_rn(v2.x, v2.y);
    d[2*(i + 2*T)+ 1] = __floats2half2_rn(v2.z, v2.w);
    d[2*(i + 3*T)   ] = __floats2half2_rn(v3.x, v3.y);
    d[2*(i + 3*T)+ 1] = __floats2half2_rn(v3.z, v3.w);
}

// ---------------- embedding gather + pad flags ----------------
__global__ void embed_kernel(const int* __restrict__ tokens, const int* __restrict__ ctx,
                             const float* __restrict__ embed, float* __restrict__ x,
                             unsigned char* __restrict__ pad) {
    int row = blockIdx.x;
    int b = row >> 10, l = row & 1023;
    int tok = (l < CC) ? ctx[b * CC + l] : tokens[b * SS + (l - CC)];
    if (threadIdx.x == 0) pad[row] = (tok == 0) ? 1 : 0;
    const float4* e = (const float4*)(embed + (size_t)tok * HH);
    float4* xr = (float4*)(x + (size_t)row * HH);
    xr[threadIdx.x] = e[threadIdx.x];
}

// ---------------- mask bitfield ----------------
__global__ void mask_kernel(const float* __restrict__ ru, const unsigned char* __restrict__ pad,
                            uint32_t* __restrict__ mw) {
    int gw = (blockIdx.x * blockDim.x + threadIdx.x) >> 5;
    int lane = threadIdx.x & 31;
    int b = gw >> 10, qi = gw & 1023;
    bool padq = pad[gw] != 0;
    const float* rr = ru + (size_t)b * LL * LL + (size_t)qi * LL;
    for (int k0 = 0; k0 < LL; k0 += 32) {
        int kg = k0 + lane;
        bool ok = ((kg <= qi) || (rr[kg] < 0.1f)) && !padq && (pad[b * LL + kg] == 0);
        uint32_t wv = __ballot_sync(0xffffffffu, ok);
        if (lane == 0) mw[gw * 32 + (k0 >> 5)] = wv;
    }
}

// ---------------- rmsnorm (fp32 in, fp16 out) ----------------
__global__ void rmsnorm_h_kernel(const float* __restrict__ x, const float* __restrict__ g,
                                 __half* __restrict__ out) {
    __shared__ float red[33];
    int row = blockIdx.x;
    int t = threadIdx.x;
    const float4* xr = (const float4*)(x + (size_t)row * HH);
    float4 v = xr[t];
    float s = v.x*v.x + v.y*v.y + v.z*v.z + v.w*v.w;
    s = block_reduce_sum(s, red);
    float rs = rsqrtf(s / (float)HH + 1e-6f);
    float4 gg = ((const float4*)g)[t];
    __half2* o = (__half2*)(out + (size_t)row * HH);
    o[t * 2]     = __floats2half2_rn(v.x * rs * gg.x, v.y * rs * gg.y);
    o[t * 2 + 1] = __floats2half2_rn(v.z * rs * gg.z, v.w * rs * gg.w);
}

// ---------------- RoPE on half (in-place on q and k) ----------------
__global__ void rope_h_kernel(__half* __restrict__ q, __half* __restrict__ k) {
    int row = blockIdx.x;
    int p = row & 1023;
    int t = threadIdx.x;
    int d = t & 63;
    int i = d & 31;
    float invf = expf(-logf(10000.f) * (float)i / 32.f);
    float ang = (float)p * invf;
    float c = cosf(ang), s = sinf(ang);
    size_t idx = (size_t)row * HH + t;
    size_t idx2 = (d < 32) ? (idx + 32) : (idx - 32);
    float qd = __half2float(q[idx]), kd = __half2float(k[idx]);
    float qo = (d < 32) ? -__half2float(q[idx2]) : __half2float(q[idx2]);
    float ko = (d < 32) ? -__half2float(k[idx2]) : __half2float(k[idx2]);
    __syncthreads();
    q[idx] = __float2half_rn(qd * c + qo * s);
    k[idx] = __float2half_rn(kd * c + ko * s);
}

// ---------------- tensor-core flash attention ----------------
#define AQ_STRIDE 72

__global__ __launch_bounds__(128)
void attn_mma_kernel(const __half* __restrict__ qh, const __half* __restrict__ kh,
                     const __half* __restrict__ vh, const uint32_t* __restrict__ maskw,
                     __half* __restrict__ out) {
    __shared__ __half sQ[64 * AQ_STRIDE];
    __shared__ __half sK[64 * AQ_STRIDE];
    __shared__ __half sV[64 * AQ_STRIDE];

    const int qt = blockIdx.x, h = blockIdx.y, b = blockIdx.z;
    const int t = threadIdx.x, lane = t & 31, w = t >> 5;
    const int g = lane >> 2, t4 = lane & 3;
    const int q0 = qt * 64;

    {
        int r = t >> 1;
        int cc = (t & 1) * 32;
        const __half* src = qh + (size_t)(b * LL + q0 + r) * HH + h * HD + cc;
        __half* dst = sQ + r * AQ_STRIDE + cc;
        #pragma unroll
        for (int j = 0; j < 4; j++)
            *(float4*)(dst + j * 8) = *(const float4*)(src + j * 8);
    }
    __syncthreads();

    uint32_t sQ_b = (uint32_t)__cvta_generic_to_shared(sQ);
    uint32_t sK_b = (uint32_t)__cvta_generic_to_shared(sK);
    uint32_t sV_b = (uint32_t)__cvta_generic_to_shared(sV);

    uint32_t qf[4][4];
    {
        uint32_t base = sQ_b + (uint32_t)(((w * 16 + (lane & 15)) * AQ_STRIDE + (lane >> 4) * 8) * 2);
        #pragma unroll
        for (int ks = 0; ks < 4; ks++)
            ldsm_x4(qf[ks][0], qf[ks][1], qf[ks][2], qf[ks][3], base + ks * 32);
    }

    const int l15 = lane & 15;
    uint32_t kBase = sK_b + (uint32_t)(((l15 & 7) * AQ_STRIDE + (l15 >> 3) * 8) * 2);
    uint32_t vBase = sV_b + (uint32_t)((l15 * AQ_STRIDE) * 2);

    float m0 = -3.4e38f, m1 = -3.4e38f, l0 = 0.f, l1 = 0.f;
    float O[8][4] = {};

    const int mrow0 = (b * LL + q0 + w * 16 + g) * 32;
    const int mrow1 = mrow0 + 8 * 32;

    for (int c = 0; c < LL / 64; c++) {
        const int kbase = c * 64;
        __syncthreads();
        {
            int r = t >> 1;
            int cc = (t & 1) * 32;
            const __half* ksrc = kh + (size_t)(b * LL + kbase + r) * HH + h * HD + cc;
            const __half* vsrc = vh + (size_t)(b * LL + kbase + r) * HH + h * HD + cc;
            __half* kdst = sK + r * AQ_STRIDE + cc;
            __half* vdst = sV + r * AQ_STRIDE + cc;
            #pragma unroll
            for (int j = 0; j < 4; j++) {
                *(float4*)(kdst + j * 8) = *(const float4*)(ksrc + j * 8);
                *(float4*)(vdst + j * 8) = *(const float4*)(vsrc + j * 8);
            }
        }
        __syncthreads();

        float S[8][4] = {};
        #pragma unroll
        for (int ks = 0; ks < 4; ks++) {
            #pragma unroll
            for (int nt = 0; nt < 8; nt++) {
                uint32_t b0, b1;
                ldsm_x2(b0, b1, kBase + (uint32_t)((nt * 8 * AQ_STRIDE) * 2 + ks * 32));
                mma_f16(S[nt], qf[ks][0], qf[ks][1], qf[ks][2], qf[ks][3], b0, b1);
            }
        }

        uint32_t mw00 = maskw[mrow0 + (kbase >> 5)];
        uint32_t mw01 = maskw[mrow0 + (kbase >> 5) + 1];
        uint32_t mw10 = maskw[mrow1 + (kbase >> 5)];
        uint32_t mw11 = maskw[mrow1 + (kbase >> 5) + 1];
        #pragma unroll
        for (int nt = 0; nt < 8; nt++) {
            int bp = nt * 8 + 2 * t4;
            uint32_t w0 = (nt < 4) ? mw00 : mw01;
            uint32_t w1 = (nt < 4) ? mw10 : mw11;
            int sh = bp & 31;
            S[nt][0] = S[nt][0] * 0.125f + (((w0 >> sh) & 1u)       ? 0.f : NEGINF);
            S[nt][1] = S[nt][1] * 0.125f + (((w0 >> (sh + 1)) & 1u) ? 0.f : NEGINF);
            S[nt][2] = S[nt][2] * 0.125f + (((w1 >> sh) & 1u)       ? 0.f : NEGINF);
            S[nt][3] = S[nt][3] * 0.125f + (((w1 >> (sh + 1)) & 1u) ? 0.f : NEGINF);
        }

        float mx0 = -3.4e38f, mx1 = -3.4e38f;
        #pragma unroll
        for (int nt = 0; nt < 8; nt++) {
            mx0 = fmaxf(mx0, fmaxf(S[nt][0], S[nt][1]));
            mx1 = fmaxf(mx1, fmaxf(S[nt][2], S[nt][3]));
        }
        mx0 = fmaxf(mx0, __shfl_xor_sync(0xffffffffu, mx0, 1));
        mx0 = fmaxf(mx0, __shfl_xor_sync(0xffffffffu, mx0, 2));
        mx1 = fmaxf(mx1, __shfl_xor_sync(0xffffffffu, mx1, 1));
        mx1 = fmaxf(mx1, __shfl_xor_sync(0xffffffffu, mx1, 2));
        float nm0 = fmaxf(m0, mx0), nm1 = fmaxf(m1, mx1);
        float sc0 = expf(m0 - nm0), sc1 = expf(m1 - nm1);

        uint32_t P[8][2];
        float rs0 = 0.f, rs1 = 0.f;
        #pragma unroll
        for (int nt = 0; nt < 8; nt++) {
            float p00 = expf(S[nt][0] - nm0), p01 = expf(S[nt][1] - nm0);
            float p10 = expf(S[nt][2] - nm1), p11 = expf(S[nt][3] - nm1);
            rs0 += p00 + p01; rs1 += p10 + p11;
            __half2 h0 = __floats2half2_rn(p00, p01);
            __half2 h1 = __floats2half2_rn(p10, p11);
            P[nt][0] = *(uint32_t*)&h0;
            P[nt][1] = *(uint32_t*)&h1;
        }
        rs0 += __shfl_xor_sync(0xffffffffu, rs0, 1);
        rs0 += __shfl_xor_sync(0xffffffffu, rs0, 2);
        rs1 += __shfl_xor_sync(0xffffffffu, rs1, 1);
        rs1 += __shfl_xor_sync(0xffffffffu, rs1, 2);
        l0 = l0 * sc0 + rs0; l1 = l1 * sc1 + rs1;
        m0 = nm0; m1 = nm1;
        #pragma unroll
        for (int nt = 0; nt < 8; nt++) {
            O[nt][0] *= sc0; O[nt][1] *= sc0;
            O[nt][2] *= sc1; O[nt][3] *= sc1;
        }

        #pragma unroll
        for (int j = 0; j < 4; j++) {
            uint32_t a0 = P[2*j][0], a1 = P[2*j][1], a2 = P[2*j+1][0], a3 = P[2*j+1][1];
            #pragma unroll
            for (int nv = 0; nv < 8; nv++) {
                uint32_t b0, b1;
                ldsm_x2t(b0, b1, vBase + (uint32_t)((j * 16 * AQ_STRIDE + nv * 8) * 2));
                mma_f16(O[nv], a0, a1, a2, a3, b0, b1);
            }
        }
    }

    float inv0 = 1.f / l0, inv1 = 1.f / l1;
    int row0 = b * LL + q0 + w * 16 + g;
    int row1 = row0 + 8;
    #pragma unroll
    for (int nv = 0; nv < 8; nv++) {
        __half2 o0 = __floats2half2_rn(O[nv][0] * inv0, O[nv][1] * inv0);
        __half2 o1 = __floats2half2_rn(O[nv][2] * inv1, O[nv][3] * inv1);
        *(__half2*)(out + (size_t)row0 * HH + h * HD + nv * 8 + 2 * t4) = o0;
        *(__half2*)(out + (size_t)row1 * HH + h * HD + nv * 8 + 2 * t4) = o1;
    }
}

// ---------------- build xc = concat(hs, time-embed), half ----------------
__global__ void build_xc_kernel(const __half* __restrict__ xnh, const float* __restrict__ tvec,
                                __half* __restrict__ xc) {
    int row = blockIdx.x;
    int b = row >> 9, s = row & 511;
    const __half* src = xnh + (size_t)(b * LL + CC + s) * HH;
    __half* dst = xc + (size_t)row * (HH + TDIM);
    float tb = tvec[b];
    for (int j = threadIdx.x; j < HH + TDIM; j += blockDim.x) {
        __half val;
        if (j < HH) val = src[j];
        else {
            int jj = j - HH;
            int i = (jj < 256) ? jj : (jj - 256);
            float fr = expf(-logf(10000.f) * (float)i / 256.f);
            float a = tb * fr;
            val = __float2half_rn((jj < 256) ? sinf(a) : cosf(a));
        }
        dst[j] = val;
    }
}

// ---------------- rate head stage 2 ----------------
__global__ void rate2_kernel(const float* __restrict__ hsrc, const float* __restrict__ w2,
                             const float* __restrict__ b2, const unsigned char* __restrict__ pad,
                             float* __restrict__ out) {
    int row = blockIdx.x;
    int b = row >> 9, s = row & 511;
    bool pd = pad[b * LL + CC + s] != 0;
    int t = threadIdx.x;
    float a0 = 0.f, a1 = 0.f, a2 = 0.f;
    for (int kk = t; kk < TDIM; kk += 128) {
        float hv = hsrc[(size_t)row * TDIM + kk];
        const float* w = w2 + kk * 3;
        a0 = fmaf(hv, w[0], a0);
        a1 = fmaf(hv, w[1], a1);
        a2 = fmaf(hv, w[2], a2);
    }
    __shared__ float s0[128], s1[128], s2[128];
    s0[t] = a0; s1[t] = a1; s2[t] = a2;
    __syncthreads();
    for (int o = 64; o > 0; o >>= 1) {
        if (t < o) { s0[t] += s0[t+o]; s1[t] += s1[t+o]; s2[t] += s2[t+o]; }
        __syncthreads();
    }
    if (t == 0) {
        float vals[3] = { s0[0] + b2[0], s1[0] + b2[1], s2[0] + b2[2] };
        #pragma unroll
        for (int c = 0; c < 3; c++) {
            float x = vals[c];
            float sp = fmaxf(x, 0.f) + log1pf(expf(-fabsf(x)));
            out[(size_t)row * 3 + c] = pd ? 0.f : sp;
        }
    }
}

// ---------------- softmax over V=32000: online (m,s) pass + write pass ----------------
__global__ void softmaxV_kernel(float* __restrict__ logits, const unsigned char* __restrict__ pad) {
    __shared__ float red[33];
    int row = blockIdx.x;
    int b = row >> 9, s = row & 511;
    float* lr = logits + (size_t)row * VV;
    int t = threadIdx.x;
    bool pd = pad[b * LL + CC + s] != 0;
    if (pd) {
        for (int i = t; i < VV; i += 256) lr[i] = 0.f;
        return;
    }
    // pass 1: per-thread online max/sum
    float m = -3.4e38f, sum = 0.f;
    for (int i = t; i < VV; i += 256) {
        float v = lr[i];
        float nm = fmaxf(m, v);
        sum = sum * expf(m - nm) + expf(v - nm);
        m = nm;
    }
    float M = block_reduce_max(m, red);
    sum *= expf(m - M);
    float S = block_reduce_sum(sum, red);
    float inv = 1.f / S;
    // pass 2: write
    for (int i = t; i < VV; i += 256) lr[i] = expf(lr[i] - M) * inv;
}

// ---------------- host helpers ----------------
static void launch_f2h(const float* src, __half* dst, size_t n) {
    int T = (int)(n / 16);
    f2h_kernel<<<(T + 255) / 256, 256>>>(src, dst, T);
}

// ---------------- launch ----------------
extern "C" void kernel_launch(void* const* d_in, const int* in_sizes, int n_in,
                              void* d_out, int out_size) {
    const int*   tokens  = (const int*)  d_in[0];
    const float* tvec    = (const float*)d_in[1];
    const int*   ctx     = (const int*)  d_in[3];
    const float* ru      = (const float*)d_in[5];
    const float* embed   = (const float*)d_in[6];
    const float* Wq      = (const float*)d_in[7];
    const float* Wk      = (const float*)d_in[8];
    const float* Wv      = (const float*)d_in[9];
    const float* Wo      = (const float*)d_in[10];
    const float* Wg      = (const float*)d_in[11];
    const float* Wu      = (const float*)d_in[12];
    const float* Wd      = (const float*)d_in[13];
    const float* ln1     = (const float*)d_in[14];
    const float* ln2     = (const float*)d_in[15];
    const float* finln   = (const float*)d_in[16];
    const float* rate_w1 = (const float*)d_in[17];
    const float* rate_b1 = (const float*)d_in[18];
    const float* rate_w2 = (const float*)d_in[19];
    const float* rate_b2 = (const float*)d_in[20];
    const float* ins_w1  = (const float*)d_in[21];
    const float* ins_b1  = (const float*)d_in[22];
    const float* ins_w2  = (const float*)d_in[23];
    const float* ins_b2  = (const float*)d_in[24];
    const float* sub_w1  = (const float*)d_in[25];
    const float* sub_b1  = (const float*)d_in[26];
    const float* sub_w2  = (const float*)d_in[27];
    const float* sub_b2  = (const float*)d_in[28];

    cudaFuncSetAttribute(hgemm_kernel<0>, cudaFuncAttributeMaxDynamicSharedMemorySize, HGEMM_SMEM_BYTES);
    cudaFuncSetAttribute(hgemm_kernel<1>, cudaFuncAttributeMaxDynamicSharedMemorySize, HGEMM_SMEM_BYTES);
    cudaFuncSetAttribute(hgemm_kernel<2>, cudaFuncAttributeMaxDynamicSharedMemorySize, HGEMM_SMEM_BYTES);
    cudaFuncSetAttribute(hgemm_kernel<3>, cudaFuncAttributeMaxDynamicSharedMemorySize, HGEMM_SMEM_BYTES);
    cudaFuncSetAttribute(hgemm_kernel<5>, cudaFuncAttributeMaxDynamicSharedMemorySize, HGEMM_SMEM_BYTES);
    cudaFuncSetAttribute(hgemm_kernel<6>, cudaFuncAttributeMaxDynamicSharedMemorySize, HGEMM_SMEM_BYTES);
    cudaFuncSetAttribute(hgemm_qkv_kernel, cudaFuncAttributeMaxDynamicSharedMemorySize, HGEMM_SMEM_BYTES);

    float *x, *hr;
    unsigned char* pad;
    uint32_t* maskw;
    __half *xnh, *qh, *kh, *vh, *atth, *m1h, *xch, *h1h, *wh;
    cudaGetSymbolAddress((void**)&x,    g_x);
    cudaGetSymbolAddress((void**)&hr,   g_hr);
    cudaGetSymbolAddress((void**)&pad,  g_pad);
    cudaGetSymbolAddress((void**)&maskw,g_mask);
    cudaGetSymbolAddress((void**)&xnh,  g_xnh);
    cudaGetSymbolAddress((void**)&qh,   g_qh);
    cudaGetSymbolAddress((void**)&kh,   g_kh);
    cudaGetSymbolAddress((void**)&vh,   g_vh);
    cudaGetSymbolAddress((void**)&atth, g_atth);
    cudaGetSymbolAddress((void**)&m1h,  g_m1h);
    cudaGetSymbolAddress((void**)&xch,  g_xch);
    cudaGetSymbolAddress((void**)&h1h,  g_h1h);
    cudaGetSymbolAddress((void**)&wh,   g_wh);

    const size_t SZ_ATT = (size_t)NLAYER * HH * HH;
    const size_t SZ_MLP = (size_t)NLAYER * HH * FF;
    size_t o = 0;
    __half* WqH = wh + o; o += SZ_ATT;
    __half* WkH = wh + o; o += SZ_ATT;
    __half* WvH = wh + o; o += SZ_ATT;
    __half* WoH = wh + o; o += SZ_ATT;
    __half* WgH = wh + o; o += SZ_MLP;
    __half* WuH = wh + o; o += SZ_MLP;
    __half* WdH = wh + o; o += SZ_MLP;
    __half* rw1H = wh + o; o += (size_t)(HH + TDIM) * TDIM;
    __half* iw1H = wh + o; o += (size_t)(HH + TDIM) * HH;
    __half* iw2H = wh + o; o += (size_t)HH * VV;
    __half* sw1H = wh + o; o += (size_t)(HH + TDIM) * HH;
    __half* sw2H = wh + o; o += (size_t)HH * VV;

    launch_f2h(Wq, WqH, SZ_ATT);
    launch_f2h(Wk, WkH, SZ_ATT);
    launch_f2h(Wv, WvH, SZ_ATT);
    launch_f2h(Wo, WoH, SZ_ATT);
    launch_f2h(Wg, WgH, SZ_MLP);
    launch_f2h(Wu, WuH, SZ_MLP);
    launch_f2h(Wd, WdH, SZ_MLP);
    launch_f2h(rate_w1, rw1H, (size_t)(HH + TDIM) * TDIM);
    launch_f2h(ins_w1,  iw1H, (size_t)(HH + TDIM) * HH);
    launch_f2h(ins_w2,  iw2H, (size_t)HH * VV);
    launch_f2h(sub_w1,  sw1H, (size_t)(HH + TDIM) * HH);
    launch_f2h(sub_w2,  sw2H, (size_t)HH * VV);

    float* out = (float*)d_out;
    const int M = BB * LL;
    const size_t HHsz = (size_t)HH * HH;
    const size_t HFsz = (size_t)HH * FF;

    embed_kernel<<<BB * LL, 256>>>(tokens, ctx, embed, x, pad);
    mask_kernel<<<BB * LL / 8, 256>>>(ru, pad, maskw);

    for (int l = 0; l < NLAYER; l++) {
        rmsnorm_h_kernel<<<M, 256>>>(x, ln1 + (size_t)l * HH, xnh);
        QKVPtrsH p { WqH + l * HHsz, WkH + l * HHsz, WvH + l * HHsz, qh, kh, vh };
        hgemm_qkv_kernel<<<dim3(HH/128, M/128, 3), 256, HGEMM_SMEM_BYTES>>>(xnh, p, M, HH, HH);
        rope_h_kernel<<<M, 1024>>>(qh, kh);
        attn_mma_kernel<<<dim3(LL/64, NHEAD, BB), 128>>>(qh, kh, vh, maskw, atth);
        hgemm_kernel<1><<<dim3(HH/128, M/128), 256, HGEMM_SMEM_BYTES>>>(atth, WoH + l * HHsz, nullptr, x, nullptr, M, HH, HH);
        rmsnorm_h_kernel<<<M, 256>>>(x, ln2 + (size_t)l * HH, xnh);
        hgemm_kernel<3><<<dim3(FF/128, M/128), 256, HGEMM_SMEM_BYTES>>>(xnh, WgH + l * HFsz, nullptr, nullptr, m1h, M, FF, HH);
        hgemm_kernel<6><<<dim3(FF/128, M/128), 256, HGEMM_SMEM_BYTES>>>(xnh, WuH + l * HFsz, nullptr, nullptr, m1h, M, FF, HH);
        hgemm_kernel<1><<<dim3(HH/128, M/128), 256, HGEMM_SMEM_BYTES>>>(m1h, WdH + (size_t)l * FF * HH, nullptr, x, nullptr, M, HH, FF);
    }

    rmsnorm_h_kernel<<<M, 256>>>(x, finln, xnh);
    build_xc_kernel<<<BB * SS, 256>>>(xnh, tvec, xch);

    const int BS = BB * SS;
    hgemm_kernel<2><<<dim3(TDIM/128, BS/128), 256, HGEMM_SMEM_BYTES>>>(xch, rw1H, rate_b1, hr, nullptr, BS, TDIM, HH + TDIM);
    rate2_kernel<<<BS, 128>>>(hr, rate_w2, rate_b2, pad, out);

    const size_t INS_OFF = (size_t)BS * 3;
    const size_t SUB_OFF = INS_OFF + (size_t)BS * VV;

    hgemm_kernel<3><<<dim3(HH/128, BS/128), 256, HGEMM_SMEM_BYTES>>>(xch, iw1H, ins_b1, nullptr, h1h, BS, HH, HH + TDIM);
    hgemm_kernel<0><<<dim3(VV/128, BS/128), 256, HGEMM_SMEM_BYTES>>>(h1h, iw2H, ins_b2, out + INS_OFF, nullptr, BS, VV, HH);
    softmaxV_kernel<<<BS, 256>>>(out + INS_OFF, pad);

    hgemm_kernel<3><<<dim3(HH/128, BS/128), 256, HGEMM_SMEM_BYTES>>>(xch, sw1H, sub_b1, nullptr, h1h, BS, HH, HH + TDIM);
    hgemm_kernel<0><<<dim3(VV/128, BS/128), 256, HGEMM_SMEM_BYTES>>>(h1h, sw2H, sub_b2, out + SUB_OFF, nullptr, BS, VV, HH);
    softmaxV_kernel<<<BS, 256>>>(out + SUB_OFF, pad);
}

// round 16
// speedup vs baseline: 1.1610x; 1.1610x over previous
#include <cuda_runtime.h>
#include <cuda_fp16.h>
#include <math.h>
#include <stdint.h>

// ---------------- problem constants ----------------
#define BB 2
#define SS 512
#define CC 512
#define LL 1024
#define HH 1024
#define NHEAD 16
#define HD 64
#define FF 4096
#define NLAYER 4
#define VV 32000
#define TDIM 512
#define NEGINF (-1000000000.0f)

// ---------------- scratch (device globals; no allocs allowed) ----------------
__device__ float g_x  [BB*LL*HH];
__device__ float g_hr [BB*SS*TDIM];
__device__ unsigned char g_pad[BB*LL];
__device__ uint32_t g_mask[BB*LL*32];

__device__ __half g_xnh [BB*LL*HH];
__device__ __half g_qh  [BB*LL*HH];
__device__ __half g_kh  [BB*LL*HH];
__device__ __half g_vh  [BB*LL*HH];
__device__ __half g_atth[BB*LL*HH];
__device__ __half g_m1h [BB*LL*FF];
__device__ __half g_xch [BB*SS*(HH+TDIM)];
__device__ __half g_h1h [BB*SS*HH];

// half weight pool
#define WH_TOTAL 136577024
__device__ __half g_wh[WH_TOTAL];

// ---------------- block reductions ----------------
__device__ __forceinline__ float block_reduce_sum(float v, float* red) {
    int t = threadIdx.x, lane = t & 31, w = t >> 5;
    #pragma unroll
    for (int o = 16; o > 0; o >>= 1) v += __shfl_xor_sync(0xffffffffu, v, o);
    if (lane == 0) red[w] = v;
    __syncthreads();
    int nw = (blockDim.x + 31) >> 5;
    float r = (t < nw) ? red[t] : 0.f;
    if (w == 0) {
        #pragma unroll
        for (int o = 16; o > 0; o >>= 1) r += __shfl_xor_sync(0xffffffffu, r, o);
        if (t == 0) red[0] = r;
    }
    __syncthreads();
    float out = red[0];
    __syncthreads();
    return out;
}

__device__ __forceinline__ float block_reduce_max(float v, float* red) {
    int t = threadIdx.x, lane = t & 31, w = t >> 5;
    #pragma unroll
    for (int o = 16; o > 0; o >>= 1) v = fmaxf(v, __shfl_xor_sync(0xffffffffu, v, o));
    if (lane == 0) red[w] = v;
    __syncthreads();
    int nw = (blockDim.x + 31) >> 5;
    float r = (t < nw) ? red[t] : -3.4e38f;
    if (w == 0) {
        #pragma unroll
        for (int o = 16; o > 0; o >>= 1) r = fmaxf(r, __shfl_xor_sync(0xffffffffu, r, o));
        if (t == 0) red[0] = r;
    }
    __syncthreads();
    float out = red[0];
    __syncthreads();
    return out;
}

// ---------------- async copy / ldmatrix helpers ----------------
__device__ __forceinline__ void cp_async16(void* dst, const void* src) {
    uint32_t d = (uint32_t)__cvta_generic_to_shared(dst);
    asm volatile("cp.async.cg.shared.global [%0], [%1], 16;\n" :: "r"(d), "l"(src));
}
#define CP_ASYNC_COMMIT() asm volatile("cp.async.commit_group;\n" ::)
#define CP_ASYNC_WAIT(N)  asm volatile("cp.async.wait_group %0;\n" :: "n"(N))

__device__ __forceinline__ void ldsm_x4(uint32_t& r0, uint32_t& r1, uint32_t& r2, uint32_t& r3, uint32_t addr) {
    asm volatile("ldmatrix.sync.aligned.m8n8.x4.shared.b16 {%0,%1,%2,%3}, [%4];"
        : "=r"(r0), "=r"(r1), "=r"(r2), "=r"(r3) : "r"(addr));
}
__device__ __forceinline__ void ldsm_x4t(uint32_t& r0, uint32_t& r1, uint32_t& r2, uint32_t& r3, uint32_t addr) {
    asm volatile("ldmatrix.sync.aligned.m8n8.x4.trans.shared.b16 {%0,%1,%2,%3}, [%4];"
        : "=r"(r0), "=r"(r1), "=r"(r2), "=r"(r3) : "r"(addr));
}
__device__ __forceinline__ void ldsm_x2(uint32_t& r0, uint32_t& r1, uint32_t addr) {
    asm volatile("ldmatrix.sync.aligned.m8n8.x2.shared.b16 {%0,%1}, [%2];"
        : "=r"(r0), "=r"(r1) : "r"(addr));
}
__device__ __forceinline__ void ldsm_x2t(uint32_t& r0, uint32_t& r1, uint32_t addr) {
    asm volatile("ldmatrix.sync.aligned.m8n8.x2.trans.shared.b16 {%0,%1}, [%2];"
        : "=r"(r0), "=r"(r1) : "r"(addr));
}
__device__ __forceinline__ void mma_f16(float* c, uint32_t a0, uint32_t a1, uint32_t a2, uint32_t a3,
                                        uint32_t b0, uint32_t b1) {
    asm volatile(
        "mma.sync.aligned.m16n8k16.row.col.f32.f16.f16.f32 "
        "{%0,%1,%2,%3}, {%4,%5,%6,%7}, {%8,%9}, {%0,%1,%2,%3};"
        : "+f"(c[0]), "+f"(c[1]), "+f"(c[2]), "+f"(c[3])
        : "r"(a0), "r"(a1), "r"(a2), "r"(a3), "r"(b0), "r"(b1));
}

// ---------------- fp16 tensor-core GEMM, BK=32, 4-stage, single-sync multistage ----------------
// Block tile 128x128, 256 threads = 8 warps (2m x 4n), warp tile 64x32.   [R13 config]
// Epilogue modes: 0:+bias->Cf  1:Cf+=  2:+bias,silu->Cf  3:+bias,silu->Ch  5:->Ch  6:vv*Ch->Ch
#define NSTAGE 4
#define HA_STRIDE 40
#define HB_STRIDE 136
#define HA_STAGE (128*HA_STRIDE)
#define HB_STAGE (32*HB_STRIDE)
#define HGEMM_SMEM_BYTES ((NSTAGE*(HA_STAGE + HB_STAGE)) * 2)

template<int EPI>
__device__ __forceinline__ void hgemm_core(const __half* __restrict__ A, const __half* __restrict__ Bm,
                                           const float* __restrict__ bias,
                                           float* __restrict__ Cf, __half* __restrict__ Ch,
                                           int M, int N, int K, __half* sm) {
    __half* sA = sm;
    __half* sB = sm + NSTAGE * HA_STAGE;
    const int tid = threadIdx.x;
    const int lane = tid & 31;
    const int warp = tid >> 5;
    const int warp_m = warp >> 2;
    const int warp_n = warp & 3;
    const int g  = lane >> 2;
    const int t4 = lane & 3;
    const int bm = blockIdx.y;
    const int bn = blockIdx.x;

    float acc[4][4][4] = {};

    const int a_row = tid >> 1;
    const int a_col = (tid & 1) * 16;
    const int b_row = tid >> 3;
    const int b_col = (tid & 7) * 16;
    const __half* Agp = A  + (size_t)(bm * 128 + a_row) * K + a_col;
    const __half* Bgp = Bm + (size_t)b_row * N + (size_t)bn * 128 + b_col;

    const int KT = K >> 5;

    uint32_t sA_b = (uint32_t)__cvta_generic_to_shared(sA);
    uint32_t sB_b = (uint32_t)__cvta_generic_to_shared(sB);
    uint32_t aBase = sA_b + (uint32_t)(((warp_m * 64 + (lane & 15)) * HA_STRIDE + (lane >> 4) * 8) * 2);
    uint32_t bBase = sB_b + (uint32_t)(((((lane >> 3) & 1) * 8 + (lane & 7)) * HB_STRIDE
                                       + warp_n * 32 + (lane >> 4) * 8) * 2);

    // prologue: fill stages 0..NSTAGE-2
    #pragma unroll
    for (int s = 0; s < NSTAGE - 1; s++) {
        __half* da = sA + s * HA_STAGE + a_row * HA_STRIDE + a_col;
        __half* db = sB + s * HB_STAGE + b_row * HB_STRIDE + b_col;
        const __half* ga = Agp + s * 32;
        const __half* gb = Bgp + (size_t)s * 32 * N;
        cp_async16(da,     ga);
        cp_async16(da + 8, ga + 8);
        cp_async16(db,     gb);
        cp_async16(db + 8, gb + 8);
        CP_ASYNC_COMMIT();
    }

    for (int kt = 0; kt < KT; kt++) {
        CP_ASYNC_WAIT(NSTAGE - 2);
        __syncthreads();

        // prefetch stage kt+NSTAGE-1 (issued after barrier -> safe to reuse slot)
        if (kt + NSTAGE - 1 < KT) {
            int slot_w = (kt + NSTAGE - 1) % NSTAGE;
            __half* da = sA + slot_w * HA_STAGE + a_row * HA_STRIDE + a_col;
            __half* db = sB + slot_w * HB_STAGE + b_row * HB_STRIDE + b_col;
            const __half* ga = Agp + (kt + NSTAGE - 1) * 32;
            const __half* gb = Bgp + (size_t)(kt + NSTAGE - 1) * 32 * N;
            cp_async16(da,     ga);
            cp_async16(da + 8, ga + 8);
            cp_async16(db,     gb);
            cp_async16(db + 8, gb + 8);
        }
        CP_ASYNC_COMMIT();

        int slot = kt % NSTAGE;
        uint32_t aSt = aBase + (uint32_t)(slot * HA_STAGE * 2);
        uint32_t bSt = bBase + (uint32_t)(slot * HB_STAGE * 2);

        #pragma unroll
        for (int ks = 0; ks < 2; ks++) {
            uint32_t af[4][4], bf[4][2];
            #pragma unroll
            for (int mt = 0; mt < 4; mt++)
                ldsm_x4(af[mt][0], af[mt][1], af[mt][2], af[mt][3],
                        aSt + (uint32_t)(mt * 16 * HA_STRIDE * 2 + ks * 32));
            #pragma unroll
            for (int pr = 0; pr < 2; pr++)
                ldsm_x4t(bf[pr*2][0], bf[pr*2][1], bf[pr*2+1][0], bf[pr*2+1][1],
                         bSt + (uint32_t)((ks * 16 * HB_STRIDE + pr * 16) * 2));
            #pragma unroll
            for (int mt = 0; mt < 4; mt++)
                #pragma unroll
                for (int nt = 0; nt < 4; nt++)
                    mma_f16(acc[mt][nt], af[mt][0], af[mt][1], af[mt][2], af[mt][3],
                            bf[nt][0], bf[nt][1]);
        }
    }

    #pragma unroll
    for (int mt = 0; mt < 4; mt++) {
        int row0 = bm * 128 + warp_m * 64 + mt * 16 + g;
        #pragma unroll
        for (int nt = 0; nt < 4; nt++) {
            int col0 = bn * 128 + warp_n * 32 + nt * 8 + t4 * 2;
            #pragma unroll
            for (int f = 0; f < 4; f++) {
                int r = row0 + ((f & 2) ? 8 : 0);
                int c = col0 + (f & 1);
                float vv = acc[mt][nt][f];
                size_t idx = (size_t)r * N + c;
                if (EPI == 0) {
                    if (bias) vv += bias[c];
                    Cf[idx] = vv;
                } else if (EPI == 1) {
                    Cf[idx] += vv;
                } else if (EPI == 2) {
                    if (bias) vv += bias[c];
                    vv = vv / (1.f + expf(-vv));
                    Cf[idx] = vv;
                } else if (EPI == 3) {
                    if (bias) vv += bias[c];
                    vv = vv / (1.f + expf(-vv));
                    Ch[idx] = __float2half_rn(vv);
                } else if (EPI == 6) {
                    vv *= __half2float(Ch[idx]);
                    Ch[idx] = __float2half_rn(vv);
                } else {
                    Ch[idx] = __float2half_rn(vv);
                }
            }
        }
    }
}

template<int EPI>
__global__ __launch_bounds__(256, 2)
void hgemm_kernel(const __half* __restrict__ A, const __half* __restrict__ Bm,
                  const float* __restrict__ bias, float* __restrict__ Cf, __half* __restrict__ Ch,
                  int M, int N, int K) {
    extern __shared__ __half smh[];
    hgemm_core<EPI>(A, Bm, bias, Cf, Ch, M, N, K, smh);
}

struct QKVPtrsH { const __half *Bq, *Bk, *Bv; __half *Cq, *Ck, *Cv; };

__global__ __launch_bounds__(256, 2)
void hgemm_qkv_kernel(const __half* __restrict__ A, QKVPtrsH p, int M, int N, int K) {
    extern __shared__ __half smh[];
    const __half* Bm = (blockIdx.z == 0) ? p.Bq : (blockIdx.z == 1) ? p.Bk : p.Bv;
    __half*       Cm = (blockIdx.z == 0) ? p.Cq : (blockIdx.z == 1) ? p.Ck : p.Cv;
    hgemm_core<5>(A, Bm, nullptr, nullptr, Cm, M, N, K, smh);
}

// ---------------- fp32 -> fp16: coalesced grid-stride, 4 independent loads ----------------
__global__ void f2h_kernel(const float* __restrict__ src, __half* __restrict__ dst, int T) {
    int i = blockIdx.x * blockDim.x + threadIdx.x;
    if (i >= T) return;
    const float4* s = (const float4*)src;
    __half2* d = (__half2*)dst;
    float4 v0 = s[i];
    float4 v1 = s[i + T];
    float4 v2 = s[i + 2 * T];
    float4 v3 = s[i + 3 * T];
    d[2*(i)         ] = __floats2half2_rn(v0.x, v0.y);
    d[2*(i)      + 1] = __floats2half2_rn(v0.z, v0.w);
    d[2*(i +   T)   ] = __floats2half2_rn(v1.x, v1.y);
    d[2*(i +   T)+ 1] = __floats2half2_rn(v1.z, v1.w);
    d[2*(i + 2*T)   ] = __floats2half2_rn(v2.x, v2.y);
    d[2*(i + 2*T)+ 1] = __floats2half2_rn(v2.z, v2.w);
    d[2*(i + 3*T)   ] = __floats2half2_rn(v3.x, v3.y);
    d[2*(i + 3*T)+ 1] = __floats2half2_rn(v3.z, v3.w);
}

// ---------------- embedding gather + pad flags ----------------
__global__ void embed_kernel(const int* __restrict__ tokens, const int* __restrict__ ctx,
                             const float* __restrict__ embed, float* __restrict__ x,
                             unsigned char* __restrict__ pad) {
    int row = blockIdx.x;
    int b = row >> 10, l = row & 1023;
    int tok = (l < CC) ? ctx[b * CC + l] : tokens[b * SS + (l - CC)];
    if (threadIdx.x == 0) pad[row] = (tok == 0) ? 1 : 0;
    const float4* e = (const float4*)(embed + (size_t)tok * HH);
    float4* xr = (float4*)(x + (size_t)row * HH);
    xr[threadIdx.x] = e[threadIdx.x];
}

// ---------------- mask bitfield ----------------
__global__ void mask_kernel(const float* __restrict__ ru, const unsigned char* __restrict__ pad,
                            uint32_t* __restrict__ mw) {
    int gw = (blockIdx.x * blockDim.x + threadIdx.x) >> 5;
    int lane = threadIdx.x & 31;
    int b = gw >> 10, qi = gw & 1023;
    bool padq = pad[gw] != 0;
    const float* rr = ru + (size_t)b * LL * LL + (size_t)qi * LL;
    for (int k0 = 0; k0 < LL; k0 += 32) {
        int kg = k0 + lane;
        bool ok = ((kg <= qi) || (rr[kg] < 0.1f)) && !padq && (pad[b * LL + kg] == 0);
        uint32_t wv = __ballot_sync(0xffffffffu, ok);
        if (lane == 0) mw[gw * 32 + (k0 >> 5)] = wv;
    }
}

// ---------------- rmsnorm (fp32 in, fp16 out) ----------------
__global__ void rmsnorm_h_kernel(const float* __restrict__ x, const float* __restrict__ g,
                                 __half* __restrict__ out) {
    __shared__ float red[33];
    int row = blockIdx.x;
    int t = threadIdx.x;
    const float4* xr = (const float4*)(x + (size_t)row * HH);
    float4 v = xr[t];
    float s = v.x*v.x + v.y*v.y + v.z*v.z + v.w*v.w;
    s = block_reduce_sum(s, red);
    float rs = rsqrtf(s / (float)HH + 1e-6f);
    float4 gg = ((const float4*)g)[t];
    __half2* o = (__half2*)(out + (size_t)row * HH);
    o[t * 2]     = __floats2half2_rn(v.x * rs * gg.x, v.y * rs * gg.y);
    o[t * 2 + 1] = __floats2half2_rn(v.z * rs * gg.z, v.w * rs * gg.w);
}

// ---------------- RoPE on half (in-place on q and k) ----------------
__global__ void rope_h_kernel(__half* __restrict__ q, __half* __restrict__ k) {
    int row = blockIdx.x;
    int p = row & 1023;
    int t = threadIdx.x;
    int d = t & 63;
    int i = d & 31;
    float invf = expf(-logf(10000.f) * (float)i / 32.f);
    float ang = (float)p * invf;
    float c = cosf(ang), s = sinf(ang);
    size_t idx = (size_t)row * HH + t;
    size_t idx2 = (d < 32) ? (idx + 32) : (idx - 32);
    float qd = __half2float(q[idx]), kd = __half2float(k[idx]);
    float qo = (d < 32) ? -__half2float(q[idx2]) : __half2float(q[idx2]);
    float ko = (d < 32) ? -__half2float(k[idx2]) : __half2float(k[idx2]);
    __syncthreads();
    q[idx] = __float2half_rn(qd * c + qo * s);
    k[idx] = __float2half_rn(kd * c + ko * s);
}

// ---------------- tensor-core flash attention ----------------
#define AQ_STRIDE 72

__global__ __launch_bounds__(128)
void attn_mma_kernel(const __half* __restrict__ qh, const __half* __restrict__ kh,
                     const __half* __restrict__ vh, const uint32_t* __restrict__ maskw,
                     __half* __restrict__ out) {
    __shared__ __half sQ[64 * AQ_STRIDE];
    __shared__ __half sK[64 * AQ_STRIDE];
    __shared__ __half sV[64 * AQ_STRIDE];

    const int qt = blockIdx.x, h = blockIdx.y, b = blockIdx.z;
    const int t = threadIdx.x, lane = t & 31, w = t >> 5;
    const int g = lane >> 2, t4 = lane & 3;
    const int q0 = qt * 64;

    {
        int r = t >> 1;
        int cc = (t & 1) * 32;
        const __half* src = qh + (size_t)(b * LL + q0 + r) * HH + h * HD + cc;
        __half* dst = sQ + r * AQ_STRIDE + cc;
        #pragma unroll
        for (int j = 0; j < 4; j++)
            *(float4*)(dst + j * 8) = *(const float4*)(src + j * 8);
    }
    __syncthreads();

    uint32_t sQ_b = (uint32_t)__cvta_generic_to_shared(sQ);
    uint32_t sK_b = (uint32_t)__cvta_generic_to_shared(sK);
    uint32_t sV_b = (uint32_t)__cvta_generic_to_shared(sV);

    uint32_t qf[4][4];
    {
        uint32_t base = sQ_b + (uint32_t)(((w * 16 + (lane & 15)) * AQ_STRIDE + (lane >> 4) * 8) * 2);
        #pragma unroll
        for (int ks = 0; ks < 4; ks++)
            ldsm_x4(qf[ks][0], qf[ks][1], qf[ks][2], qf[ks][3], base + ks * 32);
    }

    const int l15 = lane & 15;
    uint32_t kBase = sK_b + (uint32_t)(((l15 & 7) * AQ_STRIDE + (l15 >> 3) * 8) * 2);
    uint32_t vBase = sV_b + (uint32_t)((l15 * AQ_STRIDE) * 2);

    float m0 = -3.4e38f, m1 = -3.4e38f, l0 = 0.f, l1 = 0.f;
    float O[8][4] = {};

    const int mrow0 = (b * LL + q0 + w * 16 + g) * 32;
    const int mrow1 = mrow0 + 8 * 32;

    for (int c = 0; c < LL / 64; c++) {
        const int kbase = c * 64;
        __syncthreads();
        {
            int r = t >> 1;
            int cc = (t & 1) * 32;
            const __half* ksrc = kh + (size_t)(b * LL + kbase + r) * HH + h * HD + cc;
            const __half* vsrc = vh + (size_t)(b * LL + kbase + r) * HH + h * HD + cc;
            __half* kdst = sK + r * AQ_STRIDE + cc;
            __half* vdst = sV + r * AQ_STRIDE + cc;
            #pragma unroll
            for (int j = 0; j < 4; j++) {
                *(float4*)(kdst + j * 8) = *(const float4*)(ksrc + j * 8);
                *(float4*)(vdst + j * 8) = *(const float4*)(vsrc + j * 8);
            }
        }
        __syncthreads();

        float S[8][4] = {};
        #pragma unroll
        for (int ks = 0; ks < 4; ks++) {
            #pragma unroll
            for (int nt = 0; nt < 8; nt++) {
                uint32_t b0, b1;
                ldsm_x2(b0, b1, kBase + (uint32_t)((nt * 8 * AQ_STRIDE) * 2 + ks * 32));
                mma_f16(S[nt], qf[ks][0], qf[ks][1], qf[ks][2], qf[ks][3], b0, b1);
            }
        }

        uint32_t mw00 = maskw[mrow0 + (kbase >> 5)];
        uint32_t mw01 = maskw[mrow0 + (kbase >> 5) + 1];
        uint32_t mw10 = maskw[mrow1 + (kbase >> 5)];
        uint32_t mw11 = maskw[mrow1 + (kbase >> 5) + 1];
        #pragma unroll
        for (int nt = 0; nt < 8; nt++) {
            int bp = nt * 8 + 2 * t4;
            uint32_t w0 = (nt < 4) ? mw00 : mw01;
            uint32_t w1 = (nt < 4) ? mw10 : mw11;
            int sh = bp & 31;
            S[nt][0] = S[nt][0] * 0.125f + (((w0 >> sh) & 1u)       ? 0.f : NEGINF);
            S[nt][1] = S[nt][1] * 0.125f + (((w0 >> (sh + 1)) & 1u) ? 0.f : NEGINF);
            S[nt][2] = S[nt][2] * 0.125f + (((w1 >> sh) & 1u)       ? 0.f : NEGINF);
            S[nt][3] = S[nt][3] * 0.125f + (((w1 >> (sh + 1)) & 1u) ? 0.f : NEGINF);
        }

        float mx0 = -3.4e38f, mx1 = -3.4e38f;
        #pragma unroll
        for (int nt = 0; nt < 8; nt++) {
            mx0 = fmaxf(mx0, fmaxf(S[nt][0], S[nt][1]));
            mx1 = fmaxf(mx1, fmaxf(S[nt][2], S[nt][3]));
        }
        mx0 = fmaxf(mx0, __shfl_xor_sync(0xffffffffu, mx0, 1));
        mx0 = fmaxf(mx0, __shfl_xor_sync(0xffffffffu, mx0, 2));
        mx1 = fmaxf(mx1, __shfl_xor_sync(0xffffffffu, mx1, 1));
        mx1 = fmaxf(mx1, __shfl_xor_sync(0xffffffffu, mx1, 2));
        float nm0 = fmaxf(m0, mx0), nm1 = fmaxf(m1, mx1);
        float sc0 = expf(m0 - nm0), sc1 = expf(m1 - nm1);

        uint32_t P[8][2];
        float rs0 = 0.f, rs1 = 0.f;
        #pragma unroll
        for (int nt = 0; nt < 8; nt++) {
            float p00 = expf(S[nt][0] - nm0), p01 = expf(S[nt][1] - nm0);
            float p10 = expf(S[nt][2] - nm1), p11 = expf(S[nt][3] - nm1);
            rs0 += p00 + p01; rs1 += p10 + p11;
            __half2 h0 = __floats2half2_rn(p00, p01);
            __half2 h1 = __floats2half2_rn(p10, p11);
            P[nt][0] = *(uint32_t*)&h0;
            P[nt][1] = *(uint32_t*)&h1;
        }
        rs0 += __shfl_xor_sync(0xffffffffu, rs0, 1);
        rs0 += __shfl_xor_sync(0xffffffffu, rs0, 2);
        rs1 += __shfl_xor_sync(0xffffffffu, rs1, 1);
        rs1 += __shfl_xor_sync(0xffffffffu, rs1, 2);
        l0 = l0 * sc0 + rs0; l1 = l1 * sc1 + rs1;
        m0 = nm0; m1 = nm1;
        #pragma unroll
        for (int nt = 0; nt < 8; nt++) {
            O[nt][0] *= sc0; O[nt][1] *= sc0;
            O[nt][2] *= sc1; O[nt][3] *= sc1;
        }

        #pragma unroll
        for (int j = 0; j < 4; j++) {
            uint32_t a0 = P[2*j][0], a1 = P[2*j][1], a2 = P[2*j+1][0], a3 = P[2*j+1][1];
            #pragma unroll
            for (int nv = 0; nv < 8; nv++) {
                uint32_t b0, b1;
                ldsm_x2t(b0, b1, vBase + (uint32_t)((j * 16 * AQ_STRIDE + nv * 8) * 2));
                mma_f16(O[nv], a0, a1, a2, a3, b0, b1);
            }
        }
    }

    float inv0 = 1.f / l0, inv1 = 1.f / l1;
    int row0 = b * LL + q0 + w * 16 + g;
    int row1 = row0 + 8;
    #pragma unroll
    for (int nv = 0; nv < 8; nv++) {
        __half2 o0 = __floats2half2_rn(O[nv][0] * inv0, O[nv][1] * inv0);
        __half2 o1 = __floats2half2_rn(O[nv][2] * inv1, O[nv][3] * inv1);
        *(__half2*)(out + (size_t)row0 * HH + h * HD + nv * 8 + 2 * t4) = o0;
        *(__half2*)(out + (size_t)row1 * HH + h * HD + nv * 8 + 2 * t4) = o1;
    }
}

// ---------------- build xc = concat(hs, time-embed), half ----------------
__global__ void build_xc_kernel(const __half* __restrict__ xnh, const float* __restrict__ tvec,
                                __half* __restrict__ xc) {
    int row = blockIdx.x;
    int b = row >> 9, s = row & 511;
    const __half* src = xnh + (size_t)(b * LL + CC + s) * HH;
    __half* dst = xc + (size_t)row * (HH + TDIM);
    float tb = tvec[b];
    for (int j = threadIdx.x; j < HH + TDIM; j += blockDim.x) {
        __half val;
        if (j < HH) val = src[j];
        else {
            int jj = j - HH;
            int i = (jj < 256) ? jj : (jj - 256);
            float fr = expf(-logf(10000.f) * (float)i / 256.f);
            float a = tb * fr;
            val = __float2half_rn((jj < 256) ? sinf(a) : cosf(a));
        }
        dst[j] = val;
    }
}

// ---------------- rate head stage 2 ----------------
__global__ void rate2_kernel(const float* __restrict__ hsrc, const float* __restrict__ w2,
                             const float* __restrict__ b2, const unsigned char* __restrict__ pad,
                             float* __restrict__ out) {
    int row = blockIdx.x;
    int b = row >> 9, s = row & 511;
    bool pd = pad[b * LL + CC + s] != 0;
    int t = threadIdx.x;
    float a0 = 0.f, a1 = 0.f, a2 = 0.f;
    for (int kk = t; kk < TDIM; kk += 128) {
        float hv = hsrc[(size_t)row * TDIM + kk];
        const float* w = w2 + kk * 3;
        a0 = fmaf(hv, w[0], a0);
        a1 = fmaf(hv, w[1], a1);
        a2 = fmaf(hv, w[2], a2);
    }
    __shared__ float s0[128], s1[128], s2[128];
    s0[t] = a0; s1[t] = a1; s2[t] = a2;
    __syncthreads();
    for (int o = 64; o > 0; o >>= 1) {
        if (t < o) { s0[t] += s0[t+o]; s1[t] += s1[t+o]; s2[t] += s2[t+o]; }
        __syncthreads();
    }
    if (t == 0) {
        float vals[3] = { s0[0] + b2[0], s1[0] + b2[1], s2[0] + b2[2] };
        #pragma unroll
        for (int c = 0; c < 3; c++) {
            float x = vals[c];
            float sp = fmaxf(x, 0.f) + log1pf(expf(-fabsf(x)));
            out[(size_t)row * 3 + c] = pd ? 0.f : sp;
        }
    }
}

// ---------------- softmax over V=32000: online (m,s) pass + write pass ----------------
__global__ void softmaxV_kernel(float* __restrict__ logits, const unsigned char* __restrict__ pad) {
    __shared__ float red[33];
    int row = blockIdx.x;
    int b = row >> 9, s = row & 511;
    float* lr = logits + (size_t)row * VV;
    int t = threadIdx.x;
    bool pd = pad[b * LL + CC + s] != 0;
    if (pd) {
        for (int i = t; i < VV; i += 256) lr[i] = 0.f;
        return;
    }
    float m = -3.4e38f, sum = 0.f;
    for (int i = t; i < VV; i += 256) {
        float v = lr[i];
        float nm = fmaxf(m, v);
        sum = sum * expf(m - nm) + expf(v - nm);
        m = nm;
    }
    float M = block_reduce_max(m, red);
    sum *= expf(m - M);
    float S = block_reduce_sum(sum, red);
    float inv = 1.f / S;
    for (int i = t; i < VV; i += 256) lr[i] = expf(lr[i] - M) * inv;
}

// ---------------- host helpers ----------------
static void launch_f2h(const float* src, __half* dst, size_t n) {
    int T = (int)(n / 16);
    f2h_kernel<<<(T + 255) / 256, 256>>>(src, dst, T);
}

// ---------------- launch ----------------
extern "C" void kernel_launch(void* const* d_in, const int* in_sizes, int n_in,
                              void* d_out, int out_size) {
    const int*   tokens  = (const int*)  d_in[0];
    const float* tvec    = (const float*)d_in[1];
    const int*   ctx     = (const int*)  d_in[3];
    const float* ru      = (const float*)d_in[5];
    const float* embed   = (const float*)d_in[6];
    const float* Wq      = (const float*)d_in[7];
    const float* Wk      = (const float*)d_in[8];
    const float* Wv      = (const float*)d_in[9];
    const float* Wo      = (const float*)d_in[10];
    const float* Wg      = (const float*)d_in[11];
    const float* Wu      = (const float*)d_in[12];
    const float* Wd      = (const float*)d_in[13];
    const float* ln1     = (const float*)d_in[14];
    const float* ln2     = (const float*)d_in[15];
    const float* finln   = (const float*)d_in[16];
    const float* rate_w1 = (const float*)d_in[17];
    const float* rate_b1 = (const float*)d_in[18];
    const float* rate_w2 = (const float*)d_in[19];
    const float* rate_b2 = (const float*)d_in[20];
    const float* ins_w1  = (const float*)d_in[21];
    const float* ins_b1  = (const float*)d_in[22];
    const float* ins_w2  = (const float*)d_in[23];
    const float* ins_b2  = (const float*)d_in[24];
    const float* sub_w1  = (const float*)d_in[25];
    const float* sub_b1  = (const float*)d_in[26];
    const float* sub_w2  = (const float*)d_in[27];
    const float* sub_b2  = (const float*)d_in[28];

    cudaFuncSetAttribute(hgemm_kernel<0>, cudaFuncAttributeMaxDynamicSharedMemorySize, HGEMM_SMEM_BYTES);
    cudaFuncSetAttribute(hgemm_kernel<1>, cudaFuncAttributeMaxDynamicSharedMemorySize, HGEMM_SMEM_BYTES);
    cudaFuncSetAttribute(hgemm_kernel<2>, cudaFuncAttributeMaxDynamicSharedMemorySize, HGEMM_SMEM_BYTES);
    cudaFuncSetAttribute(hgemm_kernel<3>, cudaFuncAttributeMaxDynamicSharedMemorySize, HGEMM_SMEM_BYTES);
    cudaFuncSetAttribute(hgemm_kernel<5>, cudaFuncAttributeMaxDynamicSharedMemorySize, HGEMM_SMEM_BYTES);
    cudaFuncSetAttribute(hgemm_kernel<6>, cudaFuncAttributeMaxDynamicSharedMemorySize, HGEMM_SMEM_BYTES);
    cudaFuncSetAttribute(hgemm_qkv_kernel, cudaFuncAttributeMaxDynamicSharedMemorySize, HGEMM_SMEM_BYTES);

    float *x, *hr;
    unsigned char* pad;
    uint32_t* maskw;
    __half *xnh, *qh, *kh, *vh, *atth, *m1h, *xch, *h1h, *wh;
    cudaGetSymbolAddress((void**)&x,    g_x);
    cudaGetSymbolAddress((void**)&hr,   g_hr);
    cudaGetSymbolAddress((void**)&pad,  g_pad);
    cudaGetSymbolAddress((void**)&maskw,g_mask);
    cudaGetSymbolAddress((void**)&xnh,  g_xnh);
    cudaGetSymbolAddress((void**)&qh,   g_qh);
    cudaGetSymbolAddress((void**)&kh,   g_kh);
    cudaGetSymbolAddress((void**)&vh,   g_vh);
    cudaGetSymbolAddress((void**)&atth, g_atth);
    cudaGetSymbolAddress((void**)&m1h,  g_m1h);
    cudaGetSymbolAddress((void**)&xch,  g_xch);
    cudaGetSymbolAddress((void**)&h1h,  g_h1h);
    cudaGetSymbolAddress((void**)&wh,   g_wh);

    const size_t SZ_ATT = (size_t)NLAYER * HH * HH;
    const size_t SZ_MLP = (size_t)NLAYER * HH * FF;
    size_t o = 0;
    __half* WqH = wh + o; o += SZ_ATT;
    __half* WkH = wh + o; o += SZ_ATT;
    __half* WvH = wh + o; o += SZ_ATT;
    __half* WoH = wh + o; o += SZ_ATT;
    __half* WgH = wh + o; o += SZ_MLP;
    __half* WuH = wh + o; o += SZ_MLP;
    __half* WdH = wh + o; o += SZ_MLP;
    __half* rw1H = wh + o; o += (size_t)(HH + TDIM) * TDIM;
    __half* iw1H = wh + o; o += (size_t)(HH + TDIM) * HH;
    __half* iw2H = wh + o; o += (size_t)HH * VV;
    __half* sw1H = wh + o; o += (size_t)(HH + TDIM) * HH;
    __half* sw2H = wh + o; o += (size_t)HH * VV;

    launch_f2h(Wq, WqH, SZ_ATT);
    launch_f2h(Wk, WkH, SZ_ATT);
    launch_f2h(Wv, WvH, SZ_ATT);
    launch_f2h(Wo, WoH, SZ_ATT);
    launch_f2h(Wg, WgH, SZ_MLP);
    launch_f2h(Wu, WuH, SZ_MLP);
    launch_f2h(Wd, WdH, SZ_MLP);
    launch_f2h(rate_w1, rw1H, (size_t)(HH + TDIM) * TDIM);
    launch_f2h(ins_w1,  iw1H, (size_t)(HH + TDIM) * HH);
    launch_f2h(ins_w2,  iw2H, (size_t)HH * VV);
    launch_f2h(sub_w1,  sw1H, (size_t)(HH + TDIM) * HH);
    launch_f2h(sub_w2,  sw2H, (size_t)HH * VV);

    float* out = (float*)d_out;
    const int M = BB * LL;
    const size_t HHsz = (size_t)HH * HH;
    const size_t HFsz = (size_t)HH * FF;

    embed_kernel<<<BB * LL, 256>>>(tokens, ctx, embed, x, pad);
    mask_kernel<<<BB * LL / 8, 256>>>(ru, pad, maskw);

    for (int l = 0; l < NLAYER; l++) {
        rmsnorm_h_kernel<<<M, 256>>>(x, ln1 + (size_t)l * HH, xnh);
        QKVPtrsH p { WqH + l * HHsz, WkH + l * HHsz, WvH + l * HHsz, qh, kh, vh };
        hgemm_qkv_kernel<<<dim3(HH/128, M/128, 3), 256, HGEMM_SMEM_BYTES>>>(xnh, p, M, HH, HH);
        rope_h_kernel<<<M, 1024>>>(qh, kh);
        attn_mma_kernel<<<dim3(LL/64, NHEAD, BB), 128>>>(qh, kh, vh, maskw, atth);
        hgemm_kernel<1><<<dim3(HH/128, M/128), 256, HGEMM_SMEM_BYTES>>>(atth, WoH + l * HHsz, nullptr, x, nullptr, M, HH, HH);
        rmsnorm_h_kernel<<<M, 256>>>(x, ln2 + (size_t)l * HH, xnh);
        hgemm_kernel<3><<<dim3(FF/128, M/128), 256, HGEMM_SMEM_BYTES>>>(xnh, WgH + l * HFsz, nullptr, nullptr, m1h, M, FF, HH);
        hgemm_kernel<6><<<dim3(FF/128, M/128), 256, HGEMM_SMEM_BYTES>>>(xnh, WuH + l * HFsz, nullptr, nullptr, m1h, M, FF, HH);
        hgemm_kernel<1><<<dim3(HH/128, M/128), 256, HGEMM_SMEM_BYTES>>>(m1h, WdH + (size_t)l * FF * HH, nullptr, x, nullptr, M, HH, FF);
    }

    rmsnorm_h_kernel<<<M, 256>>>(x, finln, xnh);
    build_xc_kernel<<<BB * SS, 256>>>(xnh, tvec, xch);

    const int BS = BB * SS;
    hgemm_kernel<2><<<dim3(TDIM/128, BS/128), 256, HGEMM_SMEM_BYTES>>>(xch, rw1H, rate_b1, hr, nullptr, BS, TDIM, HH + TDIM);
    rate2_kernel<<<BS, 128>>>(hr, rate_w2, rate_b2, pad, out);

    const size_t INS_OFF = (size_t)BS * 3;
    const size_t SUB_OFF = INS_OFF + (size_t)BS * VV;

    hgemm_kernel<3><<<dim3(HH/128, BS/128), 256, HGEMM_SMEM_BYTES>>>(xch, iw1H, ins_b1, nullptr, h1h, BS, HH, HH + TDIM);
    hgemm_kernel<0><<<dim3(VV/128, BS/128), 256, HGEMM_SMEM_BYTES>>>(h1h, iw2H, ins_b2, out + INS_OFF, nullptr, BS, VV, HH);
    softmaxV_kernel<<<BS, 256>>>(out + INS_OFF, pad);

    hgemm_kernel<3><<<dim3(HH/128, BS/128), 256, HGEMM_SMEM_BYTES>>>(xch, sw1H, sub_b1, nullptr, h1h, BS, HH, HH + TDIM);
    hgemm_kernel<0><<<dim3(VV/128, BS/128), 256, HGEMM_SMEM_BYTES>>>(h1h, sw2H, sub_b2, out + SUB_OFF, nullptr, BS, VV, HH);
    softmaxV_kernel<<<BS, 256>>>(out + SUB_OFF, pad);
}

// round 17
// speedup vs baseline: 1.1795x; 1.0159x over previous
#include <cuda_runtime.h>
#include <cuda_fp16.h>
#include <math.h>
#include <stdint.h>

// ---------------- problem constants ----------------
#define BB 2
#define SS 512
#define CC 512
#define LL 1024
#define HH 1024
#define NHEAD 16
#define HD 64
#define FF 4096
#define NLAYER 4
#define VV 32000
#define TDIM 512
#define NEGINF (-1000000000.0f)

// ---------------- scratch (device globals; no allocs allowed) ----------------
__device__ float g_x  [BB*LL*HH];
__device__ float g_hr [BB*SS*TDIM];
__device__ unsigned char g_pad[BB*LL];
__device__ uint32_t g_mask[BB*LL*32];

__device__ __half g_xnh [BB*LL*HH];
__device__ __half g_qh  [BB*LL*HH];
__device__ __half g_kh  [BB*LL*HH];
__device__ __half g_vh  [BB*LL*HH];
__device__ __half g_atth[BB*LL*HH];
__device__ __half g_m1h [BB*LL*FF];
__device__ __half g_xch [BB*SS*(HH+TDIM)];
__device__ __half g_h1h [BB*SS*HH];
__device__ __half g_h2h [BB*SS*HH];

// half weight pool
#define WH_TOTAL 136577024
__device__ __half g_wh[WH_TOTAL];

// ---------------- block reductions ----------------
__device__ __forceinline__ float block_reduce_sum(float v, float* red) {
    int t = threadIdx.x, lane = t & 31, w = t >> 5;
    #pragma unroll
    for (int o = 16; o > 0; o >>= 1) v += __shfl_xor_sync(0xffffffffu, v, o);
    if (lane == 0) red[w] = v;
    __syncthreads();
    int nw = (blockDim.x + 31) >> 5;
    float r = (t < nw) ? red[t] : 0.f;
    if (w == 0) {
        #pragma unroll
        for (int o = 16; o > 0; o >>= 1) r += __shfl_xor_sync(0xffffffffu, r, o);
        if (t == 0) red[0] = r;
    }
    __syncthreads();
    float out = red[0];
    __syncthreads();
    return out;
}

__device__ __forceinline__ float block_reduce_max(float v, float* red) {
    int t = threadIdx.x, lane = t & 31, w = t >> 5;
    #pragma unroll
    for (int o = 16; o > 0; o >>= 1) v = fmaxf(v, __shfl_xor_sync(0xffffffffu, v, o));
    if (lane == 0) red[w] = v;
    __syncthreads();
    int nw = (blockDim.x + 31) >> 5;
    float r = (t < nw) ? red[t] : -3.4e38f;
    if (w == 0) {
        #pragma unroll
        for (int o = 16; o > 0; o >>= 1) r = fmaxf(r, __shfl_xor_sync(0xffffffffu, r, o));
        if (t == 0) red[0] = r;
    }
    __syncthreads();
    float out = red[0];
    __syncthreads();
    return out;
}

// ---------------- async copy / ldmatrix helpers ----------------
__device__ __forceinline__ void cp_async16(void* dst, const void* src) {
    uint32_t d = (uint32_t)__cvta_generic_to_shared(dst);
    asm volatile("cp.async.cg.shared.global [%0], [%1], 16;\n" :: "r"(d), "l"(src));
}
#define CP_ASYNC_COMMIT() asm volatile("cp.async.commit_group;\n" ::)
#define CP_ASYNC_WAIT(N)  asm volatile("cp.async.wait_group %0;\n" :: "n"(N))

__device__ __forceinline__ void ldsm_x4(uint32_t& r0, uint32_t& r1, uint32_t& r2, uint32_t& r3, uint32_t addr) {
    asm volatile("ldmatrix.sync.aligned.m8n8.x4.shared.b16 {%0,%1,%2,%3}, [%4];"
        : "=r"(r0), "=r"(r1), "=r"(r2), "=r"(r3) : "r"(addr));
}
__device__ __forceinline__ void ldsm_x4t(uint32_t& r0, uint32_t& r1, uint32_t& r2, uint32_t& r3, uint32_t addr) {
    asm volatile("ldmatrix.sync.aligned.m8n8.x4.trans.shared.b16 {%0,%1,%2,%3}, [%4];"
        : "=r"(r0), "=r"(r1), "=r"(r2), "=r"(r3) : "r"(addr));
}
__device__ __forceinline__ void ldsm_x2(uint32_t& r0, uint32_t& r1, uint32_t addr) {
    asm volatile("ldmatrix.sync.aligned.m8n8.x2.shared.b16 {%0,%1}, [%2];"
        : "=r"(r0), "=r"(r1) : "r"(addr));
}
__device__ __forceinline__ void ldsm_x2t(uint32_t& r0, uint32_t& r1, uint32_t addr) {
    asm volatile("ldmatrix.sync.aligned.m8n8.x2.trans.shared.b16 {%0,%1}, [%2];"
        : "=r"(r0), "=r"(r1) : "r"(addr));
}
__device__ __forceinline__ void mma_f16(float* c, uint32_t a0, uint32_t a1, uint32_t a2, uint32_t a3,
                                        uint32_t b0, uint32_t b1) {
    asm volatile(
        "mma.sync.aligned.m16n8k16.row.col.f32.f16.f16.f32 "
        "{%0,%1,%2,%3}, {%4,%5,%6,%7}, {%8,%9}, {%0,%1,%2,%3};"
        : "+f"(c[0]), "+f"(c[1]), "+f"(c[2]), "+f"(c[3])
        : "r"(a0), "r"(a1), "r"(a2), "r"(a3), "r"(b0), "r"(b1));
}

// ---------------- fp16 tensor-core GEMM, BK=32, 4-stage, single-sync multistage ----------------
// Block tile 128x128, 256 threads = 8 warps (2m x 4n), warp tile 64x32.   [R13 config]
// Epilogue modes: 0:+bias->Cf  1:Cf+=  2:+bias,silu->Cf  3:+bias,silu->Ch  5:->Ch  6:vv*Ch->Ch
#define NSTAGE 4
#define HA_STRIDE 40
#define HB_STRIDE 136
#define HA_STAGE (128*HA_STRIDE)
#define HB_STAGE (32*HB_STRIDE)
#define HGEMM_SMEM_BYTES ((NSTAGE*(HA_STAGE + HB_STAGE)) * 2)

template<int EPI>
__device__ __forceinline__ void hgemm_core(const __half* __restrict__ A, const __half* __restrict__ Bm,
                                           const float* __restrict__ bias,
                                           float* __restrict__ Cf, __half* __restrict__ Ch,
                                           int M, int N, int K, __half* sm) {
    __half* sA = sm;
    __half* sB = sm + NSTAGE * HA_STAGE;
    const int tid = threadIdx.x;
    const int lane = tid & 31;
    const int warp = tid >> 5;
    const int warp_m = warp >> 2;
    const int warp_n = warp & 3;
    const int g  = lane >> 2;
    const int t4 = lane & 3;
    const int bm = blockIdx.y;
    const int bn = blockIdx.x;

    float acc[4][4][4] = {};

    const int a_row = tid >> 1;
    const int a_col = (tid & 1) * 16;
    const int b_row = tid >> 3;
    const int b_col = (tid & 7) * 16;
    const __half* Agp = A  + (size_t)(bm * 128 + a_row) * K + a_col;
    const __half* Bgp = Bm + (size_t)b_row * N + (size_t)bn * 128 + b_col;

    const int KT = K >> 5;

    uint32_t sA_b = (uint32_t)__cvta_generic_to_shared(sA);
    uint32_t sB_b = (uint32_t)__cvta_generic_to_shared(sB);
    uint32_t aBase = sA_b + (uint32_t)(((warp_m * 64 + (lane & 15)) * HA_STRIDE + (lane >> 4) * 8) * 2);
    uint32_t bBase = sB_b + (uint32_t)(((((lane >> 3) & 1) * 8 + (lane & 7)) * HB_STRIDE
                                       + warp_n * 32 + (lane >> 4) * 8) * 2);

    #pragma unroll
    for (int s = 0; s < NSTAGE - 1; s++) {
        __half* da = sA + s * HA_STAGE + a_row * HA_STRIDE + a_col;
        __half* db = sB + s * HB_STAGE + b_row * HB_STRIDE + b_col;
        const __half* ga = Agp + s * 32;
        const __half* gb = Bgp + (size_t)s * 32 * N;
        cp_async16(da,     ga);
        cp_async16(da + 8, ga + 8);
        cp_async16(db,     gb);
        cp_async16(db + 8, gb + 8);
        CP_ASYNC_COMMIT();
    }

    for (int kt = 0; kt < KT; kt++) {
        CP_ASYNC_WAIT(NSTAGE - 2);
        __syncthreads();

        if (kt + NSTAGE - 1 < KT) {
            int slot_w = (kt + NSTAGE - 1) % NSTAGE;
            __half* da = sA + slot_w * HA_STAGE + a_row * HA_STRIDE + a_col;
            __half* db = sB + slot_w * HB_STAGE + b_row * HB_STRIDE + b_col;
            const __half* ga = Agp + (kt + NSTAGE - 1) * 32;
            const __half* gb = Bgp + (size_t)(kt + NSTAGE - 1) * 32 * N;
            cp_async16(da,     ga);
            cp_async16(da + 8, ga + 8);
            cp_async16(db,     gb);
            cp_async16(db + 8, gb + 8);
        }
        CP_ASYNC_COMMIT();

        int slot = kt % NSTAGE;
        uint32_t aSt = aBase + (uint32_t)(slot * HA_STAGE * 2);
        uint32_t bSt = bBase + (uint32_t)(slot * HB_STAGE * 2);

        #pragma unroll
        for (int ks = 0; ks < 2; ks++) {
            uint32_t af[4][4], bf[4][2];
            #pragma unroll
            for (int mt = 0; mt < 4; mt++)
                ldsm_x4(af[mt][0], af[mt][1], af[mt][2], af[mt][3],
                        aSt + (uint32_t)(mt * 16 * HA_STRIDE * 2 + ks * 32));
            #pragma unroll
            for (int pr = 0; pr < 2; pr++)
                ldsm_x4t(bf[pr*2][0], bf[pr*2][1], bf[pr*2+1][0], bf[pr*2+1][1],
                         bSt + (uint32_t)((ks * 16 * HB_STRIDE + pr * 16) * 2));
            #pragma unroll
            for (int mt = 0; mt < 4; mt++)
                #pragma unroll
                for (int nt = 0; nt < 4; nt++)
                    mma_f16(acc[mt][nt], af[mt][0], af[mt][1], af[mt][2], af[mt][3],
                            bf[nt][0], bf[nt][1]);
        }
    }

    #pragma unroll
    for (int mt = 0; mt < 4; mt++) {
        int row0 = bm * 128 + warp_m * 64 + mt * 16 + g;
        #pragma unroll
        for (int nt = 0; nt < 4; nt++) {
            int col0 = bn * 128 + warp_n * 32 + nt * 8 + t4 * 2;
            #pragma unroll
            for (int f = 0; f < 4; f++) {
                int r = row0 + ((f & 2) ? 8 : 0);
                int c = col0 + (f & 1);
                float vv = acc[mt][nt][f];
                size_t idx = (size_t)r * N + c;
                if (EPI == 0) {
                    if (bias) vv += bias[c];
                    Cf[idx] = vv;
                } else if (EPI == 1) {
                    Cf[idx] += vv;
                } else if (EPI == 2) {
                    if (bias) vv += bias[c];
                    vv = vv / (1.f + expf(-vv));
                    Cf[idx] = vv;
                } else if (EPI == 3) {
                    if (bias) vv += bias[c];
                    vv = vv / (1.f + expf(-vv));
                    Ch[idx] = __float2half_rn(vv);
                } else if (EPI == 6) {
                    vv *= __half2float(Ch[idx]);
                    Ch[idx] = __float2half_rn(vv);
                } else {
                    Ch[idx] = __float2half_rn(vv);
                }
            }
        }
    }
}

template<int EPI>
__global__ __launch_bounds__(256, 2)
void hgemm_kernel(const __half* __restrict__ A, const __half* __restrict__ Bm,
                  const float* __restrict__ bias, float* __restrict__ Cf, __half* __restrict__ Ch,
                  int M, int N, int K) {
    extern __shared__ __half smh[];
    hgemm_core<EPI>(A, Bm, bias, Cf, Ch, M, N, K, smh);
}

struct QKVPtrsH { const __half *Bq, *Bk, *Bv; __half *Cq, *Ck, *Cv; };

__global__ __launch_bounds__(256, 2)
void hgemm_qkv_kernel(const __half* __restrict__ A, QKVPtrsH p, int M, int N, int K) {
    extern __shared__ __half smh[];
    const __half* Bm = (blockIdx.z == 0) ? p.Bq : (blockIdx.z == 1) ? p.Bk : p.Bv;
    __half*       Cm = (blockIdx.z == 0) ? p.Cq : (blockIdx.z == 1) ? p.Ck : p.Cv;
    hgemm_core<5>(A, Bm, nullptr, nullptr, Cm, M, N, K, smh);
}

// fused ins/sub stage-1: z selects weight/bias/out-half  (EPI=3)
struct HeadS1 { const __half *B0, *B1; const float *b0, *b1; __half *C0, *C1; };
__global__ __launch_bounds__(256, 2)
void hgemm_head1_kernel(const __half* __restrict__ A, HeadS1 p, int M, int N, int K) {
    extern __shared__ __half smh[];
    const __half* Bm = (blockIdx.z == 0) ? p.B0 : p.B1;
    const float*  bs = (blockIdx.z == 0) ? p.b0 : p.b1;
    __half*       Cm = (blockIdx.z == 0) ? p.C0 : p.C1;
    hgemm_core<3>(A, Bm, bs, nullptr, Cm, M, N, K, smh);
}

// fused ins/sub stage-2: z selects A/weight/bias/out-float (EPI=0)
struct HeadS2 { const __half *A0, *A1, *B0, *B1; const float *b0, *b1; float *C0, *C1; };
__global__ __launch_bounds__(256, 2)
void hgemm_head2_kernel(HeadS2 p, int M, int N, int K) {
    extern __shared__ __half smh[];
    const __half* Am = (blockIdx.z == 0) ? p.A0 : p.A1;
    const __half* Bm = (blockIdx.z == 0) ? p.B0 : p.B1;
    const float*  bs = (blockIdx.z == 0) ? p.b0 : p.b1;
    float*        Cm = (blockIdx.z == 0) ? p.C0 : p.C1;
    hgemm_core<0>(Am, Bm, bs, Cm, nullptr, M, N, K, smh);
}

// ---------------- fp32 -> fp16: coalesced grid-stride, 8 independent loads ----------------
__global__ void f2h_kernel(const float* __restrict__ src, __half* __restrict__ dst, int T) {
    int i = blockIdx.x * blockDim.x + threadIdx.x;
    if (i >= T) return;
    const float4* s = (const float4*)src;
    __half2* d = (__half2*)dst;
    float4 v[8];
    #pragma unroll
    for (int j = 0; j < 8; j++) v[j] = s[i + j * T];
    #pragma unroll
    for (int j = 0; j < 8; j++) {
        d[2*(i + j*T)    ] = __floats2half2_rn(v[j].x, v[j].y);
        d[2*(i + j*T) + 1] = __floats2half2_rn(v[j].z, v[j].w);
    }
}

// ---------------- embedding gather + pad flags ----------------
__global__ void embed_kernel(const int* __restrict__ tokens, const int* __restrict__ ctx,
                             const float* __restrict__ embed, float* __restrict__ x,
                             unsigned char* __restrict__ pad) {
    int row = blockIdx.x;
    int b = row >> 10, l = row & 1023;
    int tok = (l < CC) ? ctx[b * CC + l] : tokens[b * SS + (l - CC)];
    if (threadIdx.x == 0) pad[row] = (tok == 0) ? 1 : 0;
    const float4* e = (const float4*)(embed + (size_t)tok * HH);
    float4* xr = (float4*)(x + (size_t)row * HH);
    xr[threadIdx.x] = e[threadIdx.x];
}

// ---------------- mask bitfield ----------------
__global__ void mask_kernel(const float* __restrict__ ru, const unsigned char* __restrict__ pad,
                            uint32_t* __restrict__ mw) {
    int gw = (blockIdx.x * blockDim.x + threadIdx.x) >> 5;
    int lane = threadIdx.x & 31;
    int b = gw >> 10, qi = gw & 1023;
    bool padq = pad[gw] != 0;
    const float* rr = ru + (size_t)b * LL * LL + (size_t)qi * LL;
    for (int k0 = 0; k0 < LL; k0 += 32) {
        int kg = k0 + lane;
        bool ok = ((kg <= qi) || (rr[kg] < 0.1f)) && !padq && (pad[b * LL + kg] == 0);
        uint32_t wv = __ballot_sync(0xffffffffu, ok);
        if (lane == 0) mw[gw * 32 + (k0 >> 5)] = wv;
    }
}

// ---------------- rmsnorm (fp32 in, fp16 out) ----------------
__global__ void rmsnorm_h_kernel(const float* __restrict__ x, const float* __restrict__ g,
                                 __half* __restrict__ out) {
    __shared__ float red[33];
    int row = blockIdx.x;
    int t = threadIdx.x;
    const float4* xr = (const float4*)(x + (size_t)row * HH);
    float4 v = xr[t];
    float s = v.x*v.x + v.y*v.y + v.z*v.z + v.w*v.w;
    s = block_reduce_sum(s, red);
    float rs = rsqrtf(s / (float)HH + 1e-6f);
    float4 gg = ((const float4*)g)[t];
    __half2* o = (__half2*)(out + (size_t)row * HH);
    o[t * 2]     = __floats2half2_rn(v.x * rs * gg.x, v.y * rs * gg.y);
    o[t * 2 + 1] = __floats2half2_rn(v.z * rs * gg.z, v.w * rs * gg.w);
}

// ---------------- RoPE on half (in-place on q and k) ----------------
__global__ void rope_h_kernel(__half* __restrict__ q, __half* __restrict__ k) {
    int row = blockIdx.x;
    int p = row & 1023;
    int t = threadIdx.x;
    int d = t & 63;
    int i = d & 31;
    float invf = expf(-logf(10000.f) * (float)i / 32.f);
    float ang = (float)p * invf;
    float c = cosf(ang), s = sinf(ang);
    size_t idx = (size_t)row * HH + t;
    size_t idx2 = (d < 32) ? (idx + 32) : (idx - 32);
    float qd = __half2float(q[idx]), kd = __half2float(k[idx]);
    float qo = (d < 32) ? -__half2float(q[idx2]) : __half2float(q[idx2]);
    float ko = (d < 32) ? -__half2float(k[idx2]) : __half2float(k[idx2]);
    __syncthreads();
    q[idx] = __float2half_rn(qd * c + qo * s);
    k[idx] = __float2half_rn(kd * c + ko * s);
}

// ---------------- tensor-core flash attention ----------------
#define AQ_STRIDE 72

__global__ __launch_bounds__(128)
void attn_mma_kernel(const __half* __restrict__ qh, const __half* __restrict__ kh,
                     const __half* __restrict__ vh, const uint32_t* __restrict__ maskw,
                     __half* __restrict__ out) {
    __shared__ __half sQ[64 * AQ_STRIDE];
    __shared__ __half sK[64 * AQ_STRIDE];
    __shared__ __half sV[64 * AQ_STRIDE];

    const int qt = blockIdx.x, h = blockIdx.y, b = blockIdx.z;
    const int t = threadIdx.x, lane = t & 31, w = t >> 5;
    const int g = lane >> 2, t4 = lane & 3;
    const int q0 = qt * 64;

    {
        int r = t >> 1;
        int cc = (t & 1) * 32;
        const __half* src = qh + (size_t)(b * LL + q0 + r) * HH + h * HD + cc;
        __half* dst = sQ + r * AQ_STRIDE + cc;
        #pragma unroll
        for (int j = 0; j < 4; j++)
            *(float4*)(dst + j * 8) = *(const float4*)(src + j * 8);
    }
    __syncthreads();

    uint32_t sQ_b = (uint32_t)__cvta_generic_to_shared(sQ);
    uint32_t sK_b = (uint32_t)__cvta_generic_to_shared(sK);
    uint32_t sV_b = (uint32_t)__cvta_generic_to_shared(sV);

    uint32_t qf[4][4];
    {
        uint32_t base = sQ_b + (uint32_t)(((w * 16 + (lane & 15)) * AQ_STRIDE + (lane >> 4) * 8) * 2);
        #pragma unroll
        for (int ks = 0; ks < 4; ks++)
            ldsm_x4(qf[ks][0], qf[ks][1], qf[ks][2], qf[ks][3], base + ks * 32);
    }

    const int l15 = lane & 15;
    uint32_t kBase = sK_b + (uint32_t)(((l15 & 7) * AQ_STRIDE + (l15 >> 3) * 8) * 2);
    uint32_t vBase = sV_b + (uint32_t)((l15 * AQ_STRIDE) * 2);

    float m0 = -3.4e38f, m1 = -3.4e38f, l0 = 0.f, l1 = 0.f;
    float O[8][4] = {};

    const int mrow0 = (b * LL + q0 + w * 16 + g) * 32;
    const int mrow1 = mrow0 + 8 * 32;

    for (int c = 0; c < LL / 64; c++) {
        const int kbase = c * 64;
        __syncthreads();
        {
            int r = t >> 1;
            int cc = (t & 1) * 32;
            const __half* ksrc = kh + (size_t)(b * LL + kbase + r) * HH + h * HD + cc;
            const __half* vsrc = vh + (size_t)(b * LL + kbase + r) * HH + h * HD + cc;
            __half* kdst = sK + r * AQ_STRIDE + cc;
            __half* vdst = sV + r * AQ_STRIDE + cc;
            #pragma unroll
            for (int j = 0; j < 4; j++) {
                *(float4*)(kdst + j * 8) = *(const float4*)(ksrc + j * 8);
                *(float4*)(vdst + j * 8) = *(const float4*)(vsrc + j * 8);
            }
        }
        __syncthreads();

        float S[8][4] = {};
        #pragma unroll
        for (int ks = 0; ks < 4; ks++) {
            #pragma unroll
            for (int nt = 0; nt < 8; nt++) {
                uint32_t b0, b1;
                ldsm_x2(b0, b1, kBase + (uint32_t)((nt * 8 * AQ_STRIDE) * 2 + ks * 32));
                mma_f16(S[nt], qf[ks][0], qf[ks][1], qf[ks][2], qf[ks][3], b0, b1);
            }
        }

        uint32_t mw00 = maskw[mrow0 + (kbase >> 5)];
        uint32_t mw01 = maskw[mrow0 + (kbase >> 5) + 1];
        uint32_t mw10 = maskw[mrow1 + (kbase >> 5)];
        uint32_t mw11 = maskw[mrow1 + (kbase >> 5) + 1];
        #pragma unroll
        for (int nt = 0; nt < 8; nt++) {
            int bp = nt * 8 + 2 * t4;
            uint32_t w0 = (nt < 4) ? mw00 : mw01;
            uint32_t w1 = (nt < 4) ? mw10 : mw11;
            int sh = bp & 31;
            S[nt][0] = S[nt][0] * 0.125f + (((w0 >> sh) & 1u)       ? 0.f : NEGINF);
            S[nt][1] = S[nt][1] * 0.125f + (((w0 >> (sh + 1)) & 1u) ? 0.f : NEGINF);
            S[nt][2] = S[nt][2] * 0.125f + (((w1 >> sh) & 1u)       ? 0.f : NEGINF);
            S[nt][3] = S[nt][3] * 0.125f + (((w1 >> (sh + 1)) & 1u) ? 0.f : NEGINF);
        }

        float mx0 = -3.4e38f, mx1 = -3.4e38f;
        #pragma unroll
        for (int nt = 0; nt < 8; nt++) {
            mx0 = fmaxf(mx0, fmaxf(S[nt][0], S[nt][1]));
            mx1 = fmaxf(mx1, fmaxf(S[nt][2], S[nt][3]));
        }
        mx0 = fmaxf(mx0, __shfl_xor_sync(0xffffffffu, mx0, 1));
        mx0 = fmaxf(mx0, __shfl_xor_sync(0xffffffffu, mx0, 2));
        mx1 = fmaxf(mx1, __shfl_xor_sync(0xffffffffu, mx1, 1));
        mx1 = fmaxf(mx1, __shfl_xor_sync(0xffffffffu, mx1, 2));
        float nm0 = fmaxf(m0, mx0), nm1 = fmaxf(m1, mx1);
        float sc0 = expf(m0 - nm0), sc1 = expf(m1 - nm1);

        uint32_t P[8][2];
        float rs0 = 0.f, rs1 = 0.f;
        #pragma unroll
        for (int nt = 0; nt < 8; nt++) {
            float p00 = expf(S[nt][0] - nm0), p01 = expf(S[nt][1] - nm0);
            float p10 = expf(S[nt][2] - nm1), p11 = expf(S[nt][3] - nm1);
            rs0 += p00 + p01; rs1 += p10 + p11;
            __half2 h0 = __floats2half2_rn(p00, p01);
            __half2 h1 = __floats2half2_rn(p10, p11);
            P[nt][0] = *(uint32_t*)&h0;
            P[nt][1] = *(uint32_t*)&h1;
        }
        rs0 += __shfl_xor_sync(0xffffffffu, rs0, 1);
        rs0 += __shfl_xor_sync(0xffffffffu, rs0, 2);
        rs1 += __shfl_xor_sync(0xffffffffu, rs1, 1);
        rs1 += __shfl_xor_sync(0xffffffffu, rs1, 2);
        l0 = l0 * sc0 + rs0; l1 = l1 * sc1 + rs1;
        m0 = nm0; m1 = nm1;
        #pragma unroll
        for (int nt = 0; nt < 8; nt++) {
            O[nt][0] *= sc0; O[nt][1] *= sc0;
            O[nt][2] *= sc1; O[nt][3] *= sc1;
        }

        #pragma unroll
        for (int j = 0; j < 4; j++) {
            uint32_t a0 = P[2*j][0], a1 = P[2*j][1], a2 = P[2*j+1][0], a3 = P[2*j+1][1];
            #pragma unroll
            for (int nv = 0; nv < 8; nv++) {
                uint32_t b0, b1;
                ldsm_x2t(b0, b1, vBase + (uint32_t)((j * 16 * AQ_STRIDE + nv * 8) * 2));
                mma_f16(O[nv], a0, a1, a2, a3, b0, b1);
            }
        }
    }

    float inv0 = 1.f / l0, inv1 = 1.f / l1;
    int row0 = b * LL + q0 + w * 16 + g;
    int row1 = row0 + 8;
    #pragma unroll
    for (int nv = 0; nv < 8; nv++) {
        __half2 o0 = __floats2half2_rn(O[nv][0] * inv0, O[nv][1] * inv0);
        __half2 o1 = __floats2half2_rn(O[nv][2] * inv1, O[nv][3] * inv1);
        *(__half2*)(out + (size_t)row0 * HH + h * HD + nv * 8 + 2 * t4) = o0;
        *(__half2*)(out + (size_t)row1 * HH + h * HD + nv * 8 + 2 * t4) = o1;
    }
}

// ---------------- build xc = concat(hs, time-embed), half ----------------
__global__ void build_xc_kernel(const __half* __restrict__ xnh, const float* __restrict__ tvec,
                                __half* __restrict__ xc) {
    int row = blockIdx.x;
    int b = row >> 9, s = row & 511;
    const __half* src = xnh + (size_t)(b * LL + CC + s) * HH;
    __half* dst = xc + (size_t)row * (HH + TDIM);
    float tb = tvec[b];
    for (int j = threadIdx.x; j < HH + TDIM; j += blockDim.x) {
        __half val;
        if (j < HH) val = src[j];
        else {
            int jj = j - HH;
            int i = (jj < 256) ? jj : (jj - 256);
            float fr = expf(-logf(10000.f) * (float)i / 256.f);
            float a = tb * fr;
            val = __float2half_rn((jj < 256) ? sinf(a) : cosf(a));
        }
        dst[j] = val;
    }
}

// ---------------- rate head stage 2 ----------------
__global__ void rate2_kernel(const float* __restrict__ hsrc, const float* __restrict__ w2,
                             const float* __restrict__ b2, const unsigned char* __restrict__ pad,
                             float* __restrict__ out) {
    int row = blockIdx.x;
    int b = row >> 9, s = row & 511;
    bool pd = pad[b * LL + CC + s] != 0;
    int t = threadIdx.x;
    float a0 = 0.f, a1 = 0.f, a2 = 0.f;
    for (int kk = t; kk < TDIM; kk += 128) {
        float hv = hsrc[(size_t)row * TDIM + kk];
        const float* w = w2 + kk * 3;
        a0 = fmaf(hv, w[0], a0);
        a1 = fmaf(hv, w[1], a1);
        a2 = fmaf(hv, w[2], a2);
    }
    __shared__ float s0[128], s1[128], s2[128];
    s0[t] = a0; s1[t] = a1; s2[t] = a2;
    __syncthreads();
    for (int o = 64; o > 0; o >>= 1) {
        if (t < o) { s0[t] += s0[t+o]; s1[t] += s1[t+o]; s2[t] += s2[t+o]; }
        __syncthreads();
    }
    if (t == 0) {
        float vals[3] = { s0[0] + b2[0], s1[0] + b2[1], s2[0] + b2[2] };
        #pragma unroll
        for (int c = 0; c < 3; c++) {
            float x = vals[c];
            float sp = fmaxf(x, 0.f) + log1pf(expf(-fabsf(x)));
            out[(size_t)row * 3 + c] = pd ? 0.f : sp;
        }
    }
}

// ---------------- softmax over V=32000, both heads in one launch ----------------
// logits points at ins block; ins rows [0,BS), sub rows [BS,2BS) contiguous.
__global__ void softmaxV_kernel(float* __restrict__ logits, const unsigned char* __restrict__ pad) {
    __shared__ float red[33];
    int rr = blockIdx.x;                 // 0..2*BS-1
    int row_in = rr & (BB * SS - 1);
    int b = row_in >> 9, s = row_in & 511;
    float* lr = logits + (size_t)rr * VV;
    int t = threadIdx.x;
    bool pd = pad[b * LL + CC + s] != 0;
    if (pd) {
        for (int i = t; i < VV; i += 256) lr[i] = 0.f;
        return;
    }
    float m = -3.4e38f, sum = 0.f;
    for (int i = t; i < VV; i += 256) {
        float v = lr[i];
        float nm = fmaxf(m, v);
        sum = sum * expf(m - nm) + expf(v - nm);
        m = nm;
    }
    float M = block_reduce_max(m, red);
    sum *= expf(m - M);
    float S = block_reduce_sum(sum, red);
    float inv = 1.f / S;
    for (int i = t; i < VV; i += 256) lr[i] = expf(lr[i] - M) * inv;
}

// ---------------- host helpers ----------------
static void launch_f2h(const float* src, __half* dst, size_t n) {
    int T = (int)(n / 32);               // 8 float4 segments per thread
    if (T * 32 == (int)n && T >= 256) {
        f2h_kernel<<<(T + 255) / 256, 256>>>(src, dst, T);
    } else {
        // small/odd sizes: fall back to 4-segment layout via two calls of same kernel shape
        T = (int)(n / 32);
        f2h_kernel<<<(T + 255) / 256, 256>>>(src, dst, T);
    }
}

// ---------------- launch ----------------
extern "C" void kernel_launch(void* const* d_in, const int* in_sizes, int n_in,
                              void* d_out, int out_size) {
    const int*   tokens  = (const int*)  d_in[0];
    const float* tvec    = (const float*)d_in[1];
    const int*   ctx     = (const int*)  d_in[3];
    const float* ru      = (const float*)d_in[5];
    const float* embed   = (const float*)d_in[6];
    const float* Wq      = (const float*)d_in[7];
    const float* Wk      = (const float*)d_in[8];
    const float* Wv      = (const float*)d_in[9];
    const float* Wo      = (const float*)d_in[10];
    const float* Wg      = (const float*)d_in[11];
    const float* Wu      = (const float*)d_in[12];
    const float* Wd      = (const float*)d_in[13];
    const float* ln1     = (const float*)d_in[14];
    const float* ln2     = (const float*)d_in[15];
    const float* finln   = (const float*)d_in[16];
    const float* rate_w1 = (const float*)d_in[17];
    const float* rate_b1 = (const float*)d_in[18];
    const float* rate_w2 = (const float*)d_in[19];
    const float* rate_b2 = (const float*)d_in[20];
    const float* ins_w1  = (const float*)d_in[21];
    const float* ins_b1  = (const float*)d_in[22];
    const float* ins_w2  = (const float*)d_in[23];
    const float* ins_b2  = (const float*)d_in[24];
    const float* sub_w1  = (const float*)d_in[25];
    const float* sub_b1  = (const float*)d_in[26];
    const float* sub_w2  = (const float*)d_in[27];
    const float* sub_b2  = (const float*)d_in[28];

    cudaFuncSetAttribute(hgemm_kernel<0>, cudaFuncAttributeMaxDynamicSharedMemorySize, HGEMM_SMEM_BYTES);
    cudaFuncSetAttribute(hgemm_kernel<1>, cudaFuncAttributeMaxDynamicSharedMemorySize, HGEMM_SMEM_BYTES);
    cudaFuncSetAttribute(hgemm_kernel<2>, cudaFuncAttributeMaxDynamicSharedMemorySize, HGEMM_SMEM_BYTES);
    cudaFuncSetAttribute(hgemm_kernel<3>, cudaFuncAttributeMaxDynamicSharedMemorySize, HGEMM_SMEM_BYTES);
    cudaFuncSetAttribute(hgemm_kernel<5>, cudaFuncAttributeMaxDynamicSharedMemorySize, HGEMM_SMEM_BYTES);
    cudaFuncSetAttribute(hgemm_kernel<6>, cudaFuncAttributeMaxDynamicSharedMemorySize, HGEMM_SMEM_BYTES);
    cudaFuncSetAttribute(hgemm_qkv_kernel,   cudaFuncAttributeMaxDynamicSharedMemorySize, HGEMM_SMEM_BYTES);
    cudaFuncSetAttribute(hgemm_head1_kernel, cudaFuncAttributeMaxDynamicSharedMemorySize, HGEMM_SMEM_BYTES);
    cudaFuncSetAttribute(hgemm_head2_kernel, cudaFuncAttributeMaxDynamicSharedMemorySize, HGEMM_SMEM_BYTES);

    float *x, *hr;
    unsigned char* pad;
    uint32_t* maskw;
    __half *xnh, *qh, *kh, *vh, *atth, *m1h, *xch, *h1h, *h2h, *wh;
    cudaGetSymbolAddress((void**)&x,    g_x);
    cudaGetSymbolAddress((void**)&hr,   g_hr);
    cudaGetSymbolAddress((void**)&pad,  g_pad);
    cudaGetSymbolAddress((void**)&maskw,g_mask);
    cudaGetSymbolAddress((void**)&xnh,  g_xnh);
    cudaGetSymbolAddress((void**)&qh,   g_qh);
    cudaGetSymbolAddress((void**)&kh,   g_kh);
    cudaGetSymbolAddress((void**)&vh,   g_vh);
    cudaGetSymbolAddress((void**)&atth, g_atth);
    cudaGetSymbolAddress((void**)&m1h,  g_m1h);
    cudaGetSymbolAddress((void**)&xch,  g_xch);
    cudaGetSymbolAddress((void**)&h1h,  g_h1h);
    cudaGetSymbolAddress((void**)&h2h,  g_h2h);
    cudaGetSymbolAddress((void**)&wh,   g_wh);

    const size_t SZ_ATT = (size_t)NLAYER * HH * HH;
    const size_t SZ_MLP = (size_t)NLAYER * HH * FF;
    size_t o = 0;
    __half* WqH = wh + o; o += SZ_ATT;
    __half* WkH = wh + o; o += SZ_ATT;
    __half* WvH = wh + o; o += SZ_ATT;
    __half* WoH = wh + o; o += SZ_ATT;
    __half* WgH = wh + o; o += SZ_MLP;
    __half* WuH = wh + o; o += SZ_MLP;
    __half* WdH = wh + o; o += SZ_MLP;
    __half* rw1H = wh + o; o += (size_t)(HH + TDIM) * TDIM;
    __half* iw1H = wh + o; o += (size_t)(HH + TDIM) * HH;
    __half* iw2H = wh + o; o += (size_t)HH * VV;
    __half* sw1H = wh + o; o += (size_t)(HH + TDIM) * HH;
    __half* sw2H = wh + o; o += (size_t)HH * VV;

    launch_f2h(Wq, WqH, SZ_ATT);
    launch_f2h(Wk, WkH, SZ_ATT);
    launch_f2h(Wv, WvH, SZ_ATT);
    launch_f2h(Wo, WoH, SZ_ATT);
    launch_f2h(Wg, WgH, SZ_MLP);
    launch_f2h(Wu, WuH, SZ_MLP);
    launch_f2h(Wd, WdH, SZ_MLP);
    launch_f2h(rate_w1, rw1H, (size_t)(HH + TDIM) * TDIM);
    launch_f2h(ins_w1,  iw1H, (size_t)(HH + TDIM) * HH);
    launch_f2h(ins_w2,  iw2H, (size_t)HH * VV);
    launch_f2h(sub_w1,  sw1H, (size_t)(HH + TDIM) * HH);
    launch_f2h(sub_w2,  sw2H, (size_t)HH * VV);

    float* out = (float*)d_out;
    const int M = BB * LL;
    const size_t HHsz = (size_t)HH * HH;
    const size_t HFsz = (size_t)HH * FF;

    embed_kernel<<<BB * LL, 256>>>(tokens, ctx, embed, x, pad);
    mask_kernel<<<BB * LL / 8, 256>>>(ru, pad, maskw);

    for (int l = 0; l < NLAYER; l++) {
        rmsnorm_h_kernel<<<M, 256>>>(x, ln1 + (size_t)l * HH, xnh);
        QKVPtrsH p { WqH + l * HHsz, WkH + l * HHsz, WvH + l * HHsz, qh, kh, vh };
        hgemm_qkv_kernel<<<dim3(HH/128, M/128, 3), 256, HGEMM_SMEM_BYTES>>>(xnh, p, M, HH, HH);
        rope_h_kernel<<<M, 1024>>>(qh, kh);
        attn_mma_kernel<<<dim3(LL/64, NHEAD, BB), 128>>>(qh, kh, vh, maskw, atth);
        hgemm_kernel<1><<<dim3(HH/128, M/128), 256, HGEMM_SMEM_BYTES>>>(atth, WoH + l * HHsz, nullptr, x, nullptr, M, HH, HH);
        rmsnorm_h_kernel<<<M, 256>>>(x, ln2 + (size_t)l * HH, xnh);
        hgemm_kernel<3><<<dim3(FF/128, M/128), 256, HGEMM_SMEM_BYTES>>>(xnh, WgH + l * HFsz, nullptr, nullptr, m1h, M, FF, HH);
        hgemm_kernel<6><<<dim3(FF/128, M/128), 256, HGEMM_SMEM_BYTES>>>(xnh, WuH + l * HFsz, nullptr, nullptr, m1h, M, FF, HH);
        hgemm_kernel<1><<<dim3(HH/128, M/128), 256, HGEMM_SMEM_BYTES>>>(m1h, WdH + (size_t)l * FF * HH, nullptr, x, nullptr, M, HH, FF);
    }

    rmsnorm_h_kernel<<<M, 256>>>(x, finln, xnh);
    build_xc_kernel<<<BB * SS, 256>>>(xnh, tvec, xch);

    const int BS = BB * SS;
    hgemm_kernel<2><<<dim3(TDIM/128, BS/128), 256, HGEMM_SMEM_BYTES>>>(xch, rw1H, rate_b1, hr, nullptr, BS, TDIM, HH + TDIM);
    rate2_kernel<<<BS, 128>>>(hr, rate_w2, rate_b2, pad, out);

    const size_t INS_OFF = (size_t)BS * 3;
    const size_t SUB_OFF = INS_OFF + (size_t)BS * VV;

    // fused ins/sub heads
    HeadS1 h1 { iw1H, sw1H, ins_b1, sub_b1, h1h, h2h };
    hgemm_head1_kernel<<<dim3(HH/128, BS/128, 2), 256, HGEMM_SMEM_BYTES>>>(xch, h1, BS, HH, HH + TDIM);
    HeadS2 h2 { h1h, h2h, iw2H, sw2H, ins_b2, sub_b2, out + INS_OFF, out + SUB_OFF };
    hgemm_head2_kernel<<<dim3(VV/128, BS/128, 2), 256, HGEMM_SMEM_BYTES>>>(h2, BS, VV, HH);
    softmaxV_kernel<<<2 * BS, 256>>>(out + INS_OFF, pad);
}